// round 2
// baseline (speedup 1.0000x reference)
#include <cuda_runtime.h>
#include <math.h>

// ---------------- constants ----------------
#define Sq   3072           // query seq len (8*16*24)
#define LC   768            // cache len (2*16*24)
#define LT   3840           // total kv len
#define DIMC 1536
#define NH   12
#define HD   128
#define CP   64             // pairs per head (HD/2)
#define C0P  22
#define C1P  21
#define HH   16
#define WW   24
#define HW   384            // H*W

// ---------------- scratch (device globals; no allocations) ----------------
__device__ float g_qraw[Sq * DIMC];
__device__ float g_kraw[Sq * DIMC];
__device__ float g_q[Sq * DIMC];
__device__ float g_K[LT * DIMC];
__device__ float g_V[LT * DIMC];
__device__ float g_ctx[Sq * DIMC];

// ---------------- GEMM: C[M=3072, N=1536] = A[3072,1536] @ B[1536,1536] + bias ----------------
// BM=64 BN=64 BK=16, 256 threads, 4x4 microtile
__global__ void sgemm_bias_kernel(const float* __restrict__ A,
                                  const float* __restrict__ B,
                                  const float* __restrict__ bias,
                                  float* __restrict__ C) {
    __shared__ __align__(16) float As[16][64];
    __shared__ __align__(16) float Bs[16][64];

    const int bx = blockIdx.x;   // N tile (24)
    const int by = blockIdx.y;   // M tile (48)
    const int t  = threadIdx.x;
    const int tx = t & 15;
    const int ty = t >> 4;

    const int arow  = t >> 2;          // 0..63
    const int acol4 = (t & 3) << 2;    // 0,4,8,12
    const int brow  = t >> 4;          // 0..15
    const int bcol4 = (t & 15) << 2;   // 0..60

    const float* Aptr = A + (by * 64 + arow) * DIMC;
    const float* Bptr = B + brow * DIMC + bx * 64 + bcol4;

    float acc[4][4] = {};

    for (int k0 = 0; k0 < DIMC; k0 += 16) {
        float4 av = *(const float4*)(Aptr + k0 + acol4);
        As[acol4 + 0][arow] = av.x;
        As[acol4 + 1][arow] = av.y;
        As[acol4 + 2][arow] = av.z;
        As[acol4 + 3][arow] = av.w;
        *(float4*)&Bs[brow][bcol4] = *(const float4*)(Bptr + (size_t)k0 * DIMC);
        __syncthreads();
#pragma unroll
        for (int k = 0; k < 16; k++) {
            float4 a4 = *(const float4*)&As[k][ty << 2];
            float4 b4 = *(const float4*)&Bs[k][tx << 2];
            float a[4] = {a4.x, a4.y, a4.z, a4.w};
            float b[4] = {b4.x, b4.y, b4.z, b4.w};
#pragma unroll
            for (int i = 0; i < 4; i++)
#pragma unroll
                for (int j = 0; j < 4; j++) acc[i][j] += a[i] * b[j];
        }
        __syncthreads();
    }

#pragma unroll
    for (int i = 0; i < 4; i++) {
        int row = by * 64 + (ty << 2) + i;
#pragma unroll
        for (int j = 0; j < 4; j++) {
            int col = bx * 64 + (tx << 2) + j;
            C[(size_t)row * DIMC + col] = acc[i][j] + bias[col];
        }
    }
}

// ---------------- RMSNorm + RoPE ----------------
__inline__ __device__ float block_reduce_sum(float v) {
    __shared__ float red[8];
#pragma unroll
    for (int o = 16; o > 0; o >>= 1) v += __shfl_xor_sync(0xffffffffu, v, o);
    int wid = threadIdx.x >> 5, lane = threadIdx.x & 31;
    if (lane == 0) red[wid] = v;
    __syncthreads();
    if (wid == 0) {
        v = (lane < 8) ? red[lane] : 0.f;
#pragma unroll
        for (int o = 4; o > 0; o >>= 1) v += __shfl_xor_sync(0xffffffffu, v, o);
        if (lane == 0) red[0] = v;
    }
    __syncthreads();
    return red[0];
}

__global__ void norm_rope_kernel(const float* __restrict__ in,
                                 const float* __restrict__ w,
                                 const float* __restrict__ fcos,
                                 const float* __restrict__ fsin,
                                 float* __restrict__ out) {
    const int s = blockIdx.x;
    const int t = threadIdx.x;
    const float* row = in + (size_t)s * DIMC;

    float ss = 0.f;
    for (int j = t; j < DIMC / 4; j += 256) {
        float4 v = *(const float4*)(row + j * 4);
        ss += v.x * v.x + v.y * v.y + v.z * v.z + v.w * v.w;
    }
    ss = block_reduce_sum(ss);
    const float scale = rsqrtf(ss * (1.0f / DIMC) + 1e-6f);

    const int f   = s / HW;
    const int rem = s - f * HW;
    const int h   = rem / WW;
    const int wp  = rem - h * WW;

    for (int p = t; p < DIMC / 2; p += 256) {
        int c = p & (CP - 1);
        int pos = (c < C0P) ? f : (c < C0P + C1P) ? h : wp;
        float fc = fcos[pos * CP + c];
        float fs = fsin[pos * CP + c];
        float a = row[2 * p]     * scale * w[2 * p];
        float b = row[2 * p + 1] * scale * w[2 * p + 1];
        out[(size_t)s * DIMC + 2 * p]     = a * fc - b * fs;
        out[(size_t)s * DIMC + 2 * p + 1] = a * fs + b * fc;
    }
}

// ---------------- cache prep: RoPE(prev_k)*mask -> K[0:768], prev_v*mask -> V[0:768] ----------------
__global__ void cache_prep_kernel(const float* __restrict__ pk,
                                  const float* __restrict__ pv,
                                  const float* __restrict__ fcos,
                                  const float* __restrict__ fsin,
                                  const int* __restrict__ hm,
                                  const int* __restrict__ shift_ptr) {
    const int l = blockIdx.x;   // 0..767
    const int t = threadIdx.x;
    const int shift = *shift_ptr;

    const int f   = l / HW;
    const int rem = l - f * HW;
    const int h   = rem / WW;
    const int wp  = rem - h * WW;

    for (int p = t; p < DIMC / 2; p += 256) {
        int n = p >> 6;            // head
        int c = p & (CP - 1);
        float m = (hm[n] != 0) ? 1.f : 0.f;
        int pos = (c < C0P) ? (shift + f) : (c < C0P + C1P) ? h : wp;
        float fc = fcos[pos * CP + c];
        float fs = fsin[pos * CP + c];
        float a = pk[(size_t)l * DIMC + 2 * p];
        float b = pk[(size_t)l * DIMC + 2 * p + 1];
        g_K[(size_t)l * DIMC + 2 * p]     = (a * fc - b * fs) * m;
        g_K[(size_t)l * DIMC + 2 * p + 1] = (a * fs + b * fc) * m;
    }
    for (int j = t; j < DIMC / 4; j += 256) {
        float4 v = *(const float4*)(pv + (size_t)l * DIMC + j * 4);
        int n = (j * 4) >> 7;
        float m = (hm[n] != 0) ? 1.f : 0.f;
        v.x *= m; v.y *= m; v.z *= m; v.w *= m;
        *(float4*)(g_V + (size_t)l * DIMC + j * 4) = v;
    }
}

// ---------------- flash attention (fp32) ----------------
// grid (48 q-tiles, 12 heads), 256 threads. 64-row q tile, 64-row kv tiles.
#define ATTN_SMEM_FLOATS (128 * 64 + 128 * 64 + 64 * 128 + 64 * 65)

__global__ void attn_kernel(const float* __restrict__ Q,
                            const float* __restrict__ Kc,
                            const float* __restrict__ Vc,
                            float* __restrict__ O) {
    extern __shared__ __align__(16) float sm[];
    float* Qt = sm;                   // [128][64] transposed
    float* Kt = Qt + 128 * 64;        // [128][64] transposed
    float* Vs = Kt + 128 * 64;        // [64][128]
    float* Ps = Vs + 64 * 128;        // [64][65]

    const int qt = blockIdx.x;
    const int n  = blockIdx.y;
    const int t  = threadIdx.x;
    const int tx = t & 15;
    const int ty = t >> 4;

    // load Q tile (transposed)
    {
        int r = t >> 2, seg = t & 3;
        const float* qrow = Q + (size_t)(qt * 64 + r) * DIMC + n * HD + seg * 32;
#pragma unroll
        for (int u = 0; u < 8; u++) {
            float4 v = *(const float4*)(qrow + u * 4);
            int d = seg * 32 + u * 4;
            Qt[(d + 0) * 64 + r] = v.x;
            Qt[(d + 1) * 64 + r] = v.y;
            Qt[(d + 2) * 64 + r] = v.z;
            Qt[(d + 3) * 64 + r] = v.w;
        }
    }

    float rm[4], rl[4], o[4][8];
#pragma unroll
    for (int i = 0; i < 4; i++) {
        rm[i] = -1e30f;
        rl[i] = 0.f;
#pragma unroll
        for (int j = 0; j < 8; j++) o[i][j] = 0.f;
    }
    const float scale = 0.08838834764831845f;  // 1/sqrt(128)

    for (int kt = 0; kt < LT / 64; kt++) {
        __syncthreads();
        // load K tile transposed
        {
            int r = t >> 2, seg = t & 3;
            const float* krow = Kc + (size_t)(kt * 64 + r) * DIMC + n * HD + seg * 32;
#pragma unroll
            for (int u = 0; u < 8; u++) {
                float4 v = *(const float4*)(krow + u * 4);
                int d = seg * 32 + u * 4;
                Kt[(d + 0) * 64 + r] = v.x;
                Kt[(d + 1) * 64 + r] = v.y;
                Kt[(d + 2) * 64 + r] = v.z;
                Kt[(d + 3) * 64 + r] = v.w;
            }
        }
        // load V tile [64][128]
#pragma unroll
        for (int u = 0; u < 8; u++) {
            int idx = t + u * 256;          // float4 index in [0,2048)
            int vr = idx >> 5, vc4 = idx & 31;
            *(float4*)&Vs[vr * 128 + vc4 * 4] =
                *(const float4*)(Vc + (size_t)(kt * 64 + vr) * DIMC + n * HD + vc4 * 4);
        }
        __syncthreads();

        // S = Q K^T (64x64, k=128)
        float s[4][4] = {};
#pragma unroll 4
        for (int d = 0; d < 128; d++) {
            float4 a4 = *(const float4*)&Qt[d * 64 + (ty << 2)];
            float4 b4 = *(const float4*)&Kt[d * 64 + (tx << 2)];
            float a[4] = {a4.x, a4.y, a4.z, a4.w};
            float b[4] = {b4.x, b4.y, b4.z, b4.w};
#pragma unroll
            for (int i = 0; i < 4; i++)
#pragma unroll
                for (int j = 0; j < 4; j++) s[i][j] += a[i] * b[j];
        }

        // online softmax
        float p[4][4];
#pragma unroll
        for (int i = 0; i < 4; i++) {
#pragma unroll
            for (int j = 0; j < 4; j++) s[i][j] *= scale;
            float tm = fmaxf(fmaxf(s[i][0], s[i][1]), fmaxf(s[i][2], s[i][3]));
#pragma unroll
            for (int off = 1; off < 16; off <<= 1)
                tm = fmaxf(tm, __shfl_xor_sync(0xffffffffu, tm, off, 16));
            float nm = fmaxf(rm[i], tm);
            float corr = __expf(rm[i] - nm);
            float psum = 0.f;
#pragma unroll
            for (int j = 0; j < 4; j++) {
                p[i][j] = __expf(s[i][j] - nm);
                psum += p[i][j];
            }
#pragma unroll
            for (int off = 1; off < 16; off <<= 1)
                psum += __shfl_xor_sync(0xffffffffu, psum, off, 16);
            rl[i] = rl[i] * corr + psum;
            rm[i] = nm;
#pragma unroll
            for (int j = 0; j < 8; j++) o[i][j] *= corr;
        }

        // stash P
#pragma unroll
        for (int i = 0; i < 4; i++)
#pragma unroll
            for (int j = 0; j < 4; j++)
                Ps[((ty << 2) + i) * 65 + (tx << 2) + j] = p[i][j];
        __syncthreads();

        // O += P V
#pragma unroll 4
        for (int kk = 0; kk < 64; kk++) {
            float4 v0 = *(const float4*)&Vs[kk * 128 + (tx << 3)];
            float4 v1 = *(const float4*)&Vs[kk * 128 + (tx << 3) + 4];
#pragma unroll
            for (int i = 0; i < 4; i++) {
                float pi = Ps[((ty << 2) + i) * 65 + kk];
                o[i][0] += pi * v0.x; o[i][1] += pi * v0.y;
                o[i][2] += pi * v0.z; o[i][3] += pi * v0.w;
                o[i][4] += pi * v1.x; o[i][5] += pi * v1.y;
                o[i][6] += pi * v1.z; o[i][7] += pi * v1.w;
            }
        }
    }

    // epilogue
#pragma unroll
    for (int i = 0; i < 4; i++) {
        float inv = 1.f / rl[i];
        int row = qt * 64 + (ty << 2) + i;
        float* dst = O + (size_t)row * DIMC + n * HD + (tx << 3);
#pragma unroll
        for (int j = 0; j < 8; j++) dst[j] = o[i][j] * inv;
    }
}

// ---------------- launch ----------------
extern "C" void kernel_launch(void* const* d_in, const int* in_sizes, int n_in,
                              void* d_out, int out_size) {
    const float* x    = (const float*)d_in[0];
    const float* Wq   = (const float*)d_in[1];
    const float* bq   = (const float*)d_in[2];
    const float* Wk   = (const float*)d_in[3];
    const float* bk   = (const float*)d_in[4];
    const float* Wv   = (const float*)d_in[5];
    const float* bv   = (const float*)d_in[6];
    const float* Wo   = (const float*)d_in[7];
    const float* bo   = (const float*)d_in[8];
    const float* wqn  = (const float*)d_in[9];
    const float* wkn  = (const float*)d_in[10];
    const float* pk   = (const float*)d_in[11];
    const float* pv   = (const float*)d_in[12];
    const float* fcos = (const float*)d_in[13];
    const float* fsin = (const float*)d_in[14];
    const int*   hm   = (const int*)d_in[15];
    const int* shift  = (const int*)d_in[18];
    float* out = (float*)d_out;

    float *qraw, *kraw, *q, *K, *V, *ctx;
    cudaGetSymbolAddress((void**)&qraw, g_qraw);
    cudaGetSymbolAddress((void**)&kraw, g_kraw);
    cudaGetSymbolAddress((void**)&q,    g_q);
    cudaGetSymbolAddress((void**)&K,    g_K);
    cudaGetSymbolAddress((void**)&V,    g_V);
    cudaGetSymbolAddress((void**)&ctx,  g_ctx);

    dim3 ggrid(DIMC / 64, Sq / 64);
    sgemm_bias_kernel<<<ggrid, 256>>>(x, Wq, bq, qraw);
    sgemm_bias_kernel<<<ggrid, 256>>>(x, Wk, bk, kraw);
    sgemm_bias_kernel<<<ggrid, 256>>>(x, Wv, bv, V + (size_t)LC * DIMC);

    norm_rope_kernel<<<Sq, 256>>>(qraw, wqn, fcos, fsin, q);
    norm_rope_kernel<<<Sq, 256>>>(kraw, wkn, fcos, fsin, K + (size_t)LC * DIMC);

    cache_prep_kernel<<<LC, 256>>>(pk, pv, fcos, fsin, hm, shift);

    const int smem = ATTN_SMEM_FLOATS * 4;
    cudaFuncSetAttribute(attn_kernel, cudaFuncAttributeMaxDynamicSharedMemorySize, smem);
    attn_kernel<<<dim3(Sq / 64, NH), 256, smem>>>(q, K, V, ctx);

    sgemm_bias_kernel<<<ggrid, 256>>>(ctx, Wo, bo, out);
}

// round 4
// speedup vs baseline: 3.7407x; 3.7407x over previous
#include <cuda_runtime.h>
#include <math.h>
#include <stdint.h>

// ---------------- constants ----------------
#define Sq   3072
#define LC   768
#define LT   3840
#define DIMC 1536
#define NH   12
#define HD   128
#define CP   64
#define C0P  22
#define C1P  21
#define WW   24
#define HW   384

// ---------------- scratch ----------------
__device__ float g_qraw[Sq * DIMC];
__device__ float g_kraw[Sq * DIMC];
__device__ float g_q[Sq * DIMC];
__device__ float g_K[LT * DIMC];
__device__ float g_V[LT * DIMC];
__device__ float g_ctx[Sq * DIMC];
__device__ float g_xr[Sq * DIMC];
__device__ float g_Wqr[DIMC * DIMC];
__device__ float g_Wkr[DIMC * DIMC];
__device__ float g_Wvr[DIMC * DIMC];
__device__ float g_Wor[DIMC * DIMC];

// ---------------- helpers ----------------
__device__ __forceinline__ float tf32r(float x) {
    uint32_t r;
    asm("cvt.rna.tf32.f32 %0, %1;" : "=r"(r) : "f"(x));
    return __uint_as_float(r);
}
__device__ __forceinline__ uint32_t fbits(float x) { return __float_as_uint(x); }

__device__ __forceinline__ void mma_tf32(float* d, const uint32_t* a, const uint32_t* b) {
    asm volatile(
        "mma.sync.aligned.m16n8k8.row.col.f32.tf32.tf32.f32 "
        "{%0,%1,%2,%3}, {%4,%5,%6,%7}, {%8,%9}, {%0,%1,%2,%3};\n"
        : "+f"(d[0]), "+f"(d[1]), "+f"(d[2]), "+f"(d[3])
        : "r"(a[0]), "r"(a[1]), "r"(a[2]), "r"(a[3]), "r"(b[0]), "r"(b[1]));
}

__device__ __forceinline__ void cpa16(void* s, const void* g) {
    uint32_t sa = (uint32_t)__cvta_generic_to_shared(s);
    asm volatile("cp.async.cg.shared.global [%0], [%1], 16;" :: "r"(sa), "l"(g));
}

// ---------------- tf32 rounding pass ----------------
__global__ void round_tf32_kernel(const float* __restrict__ in, float* __restrict__ out, int n4) {
    int i = blockIdx.x * blockDim.x + threadIdx.x;
    if (i < n4) {
        float4 v = ((const float4*)in)[i];
        v.x = tf32r(v.x); v.y = tf32r(v.y); v.z = tf32r(v.z); v.w = tf32r(v.w);
        ((float4*)out)[i] = v;
    }
}

// ---------------- TF32 GEMM: C[3072,1536] = A @ B + bias ----------------
#define GBM 128
#define GBN 128
#define GBK 32
#define AP  36
#define BP  136
#define GEMM_SMEM ((2 * GBM * AP + 2 * GBK * BP) * 4)

__global__ __launch_bounds__(256) void tf32_gemm_kernel(
    const float* __restrict__ A, const float* __restrict__ B,
    const float* __restrict__ bias, float* __restrict__ C, int round_out) {
    extern __shared__ float sm[];
    float* As = sm;                   // [2][GBM][AP]
    float* Bs = sm + 2 * GBM * AP;    // [2][GBK][BP]

    const int bx = blockIdx.x, by = blockIdx.y;
    const int t = threadIdx.x;
    const int w = t >> 5, lane = t & 31, g = lane >> 2, tg = lane & 3;
    const int wm = w >> 1, wn = w & 1;

    const int ar = t >> 3, ac4 = t & 7;       // A: 32 rows/pass, 8 float4 cols
    const int br = t >> 5, bc4 = t & 31;      // B: 8 rows/pass, 32 float4 cols

    float acc[2][8][4];
#pragma unroll
    for (int mi = 0; mi < 2; mi++)
#pragma unroll
        for (int nj = 0; nj < 8; nj++)
#pragma unroll
            for (int r = 0; r < 4; r++) acc[mi][nj][r] = 0.f;

    // prologue loads (buf 0)
    {
        const float* srcA = A + (size_t)(by * GBM + ar) * DIMC + ac4 * 4;
        float* dstA = As + ar * AP + ac4 * 4;
#pragma unroll
        for (int i = 0; i < 4; i++) cpa16(dstA + i * 32 * AP, srcA + (size_t)i * 32 * DIMC);
        const float* srcB = B + (size_t)br * DIMC + bx * GBN + bc4 * 4;
        float* dstB = Bs + br * BP + bc4 * 4;
#pragma unroll
        for (int i = 0; i < 4; i++) cpa16(dstB + i * 8 * BP, srcB + (size_t)i * 8 * DIMC);
    }
    asm volatile("cp.async.commit_group;");

    const int NIT = DIMC / GBK;
    for (int it = 0; it < NIT; it++) {
        asm volatile("cp.async.wait_group 0;");
        __syncthreads();
        if (it + 1 < NIT) {
            int k0 = (it + 1) * GBK;
            int buf = (it + 1) & 1;
            const float* srcA = A + (size_t)(by * GBM + ar) * DIMC + k0 + ac4 * 4;
            float* dstA = As + buf * GBM * AP + ar * AP + ac4 * 4;
#pragma unroll
            for (int i = 0; i < 4; i++) cpa16(dstA + i * 32 * AP, srcA + (size_t)i * 32 * DIMC);
            const float* srcB = B + (size_t)(k0 + br) * DIMC + bx * GBN + bc4 * 4;
            float* dstB = Bs + buf * GBK * BP + br * BP + bc4 * 4;
#pragma unroll
            for (int i = 0; i < 4; i++) cpa16(dstB + i * 8 * BP, srcB + (size_t)i * 8 * DIMC);
        }
        asm volatile("cp.async.commit_group;");

        const float* Ab = As + (it & 1) * GBM * AP;
        const float* Bb = Bs + (it & 1) * GBK * BP;
#pragma unroll
        for (int ks = 0; ks < 4; ks++) {
            const int k = ks * 8;
            uint32_t af[2][4];
#pragma unroll
            for (int mi = 0; mi < 2; mi++) {
                int rb = wm * 32 + mi * 16;
                af[mi][0] = fbits(Ab[(rb + g) * AP + k + tg]);
                af[mi][1] = fbits(Ab[(rb + g + 8) * AP + k + tg]);
                af[mi][2] = fbits(Ab[(rb + g) * AP + k + tg + 4]);
                af[mi][3] = fbits(Ab[(rb + g + 8) * AP + k + tg + 4]);
            }
#pragma unroll
            for (int nj = 0; nj < 8; nj++) {
                int col = wn * 64 + nj * 8 + g;
                uint32_t bf[2];
                bf[0] = fbits(Bb[(k + tg) * BP + col]);
                bf[1] = fbits(Bb[(k + tg + 4) * BP + col]);
                mma_tf32(acc[0][nj], af[0], bf);
                mma_tf32(acc[1][nj], af[1], bf);
            }
        }
    }

#pragma unroll
    for (int mi = 0; mi < 2; mi++) {
#pragma unroll
        for (int half = 0; half < 2; half++) {
            int row = by * GBM + wm * 32 + mi * 16 + g + half * 8;
#pragma unroll
            for (int nj = 0; nj < 8; nj++) {
                int col = bx * GBN + wn * 64 + nj * 8 + 2 * tg;
                float v0 = acc[mi][nj][half * 2 + 0] + bias[col];
                float v1 = acc[mi][nj][half * 2 + 1] + bias[col + 1];
                if (round_out) { v0 = tf32r(v0); v1 = tf32r(v1); }
                *(float2*)(C + (size_t)row * DIMC + col) = make_float2(v0, v1);
            }
        }
    }
}

// ---------------- RMSNorm + RoPE (rounds output to tf32) ----------------
__inline__ __device__ float block_reduce_sum(float v) {
    __shared__ float red[8];
#pragma unroll
    for (int o = 16; o > 0; o >>= 1) v += __shfl_xor_sync(0xffffffffu, v, o);
    int wid = threadIdx.x >> 5, lane = threadIdx.x & 31;
    if (lane == 0) red[wid] = v;
    __syncthreads();
    if (wid == 0) {
        v = (lane < 8) ? red[lane] : 0.f;
#pragma unroll
        for (int o = 4; o > 0; o >>= 1) v += __shfl_xor_sync(0xffffffffu, v, o);
        if (lane == 0) red[0] = v;
    }
    __syncthreads();
    return red[0];
}

__global__ void norm_rope_kernel(const float* __restrict__ in,
                                 const float* __restrict__ w,
                                 const float* __restrict__ fcos,
                                 const float* __restrict__ fsin,
                                 float* __restrict__ out) {
    const int s = blockIdx.x;
    const int t = threadIdx.x;
    const float* row = in + (size_t)s * DIMC;

    float ss = 0.f;
    for (int j = t; j < DIMC / 4; j += 256) {
        float4 v = *(const float4*)(row + j * 4);
        ss += v.x * v.x + v.y * v.y + v.z * v.z + v.w * v.w;
    }
    ss = block_reduce_sum(ss);
    const float scale = rsqrtf(ss * (1.0f / DIMC) + 1e-6f);

    const int f = s / HW;
    const int rem = s - f * HW;
    const int h = rem / WW;
    const int wp = rem - h * WW;

    for (int p = t; p < DIMC / 2; p += 256) {
        int c = p & (CP - 1);
        int pos = (c < C0P) ? f : (c < C0P + C1P) ? h : wp;
        float fc = fcos[pos * CP + c];
        float fs = fsin[pos * CP + c];
        float a = row[2 * p] * scale * w[2 * p];
        float b = row[2 * p + 1] * scale * w[2 * p + 1];
        out[(size_t)s * DIMC + 2 * p]     = tf32r(a * fc - b * fs);
        out[(size_t)s * DIMC + 2 * p + 1] = tf32r(a * fs + b * fc);
    }
}

// ---------------- cache prep (rounds outputs) ----------------
__global__ void cache_prep_kernel(const float* __restrict__ pk,
                                  const float* __restrict__ pv,
                                  const float* __restrict__ fcos,
                                  const float* __restrict__ fsin,
                                  const int* __restrict__ hm,
                                  const int* __restrict__ shift_ptr) {
    const int l = blockIdx.x;
    const int t = threadIdx.x;
    const int shift = *shift_ptr;

    const int f = l / HW;
    const int rem = l - f * HW;
    const int h = rem / WW;
    const int wp = rem - h * WW;

    for (int p = t; p < DIMC / 2; p += 256) {
        int n = p >> 6;
        int c = p & (CP - 1);
        float m = (hm[n] != 0) ? 1.f : 0.f;
        int pos = (c < C0P) ? (shift + f) : (c < C0P + C1P) ? h : wp;
        float fc = fcos[pos * CP + c];
        float fs = fsin[pos * CP + c];
        float a = pk[(size_t)l * DIMC + 2 * p];
        float b = pk[(size_t)l * DIMC + 2 * p + 1];
        g_K[(size_t)l * DIMC + 2 * p]     = tf32r((a * fc - b * fs) * m);
        g_K[(size_t)l * DIMC + 2 * p + 1] = tf32r((a * fs + b * fc) * m);
    }
    for (int j = t; j < DIMC / 4; j += 256) {
        float4 v = *(const float4*)(pv + (size_t)l * DIMC + j * 4);
        int n = (j * 4) >> 7;
        float m = (hm[n] != 0) ? 1.f : 0.f;
        v.x = tf32r(v.x * m); v.y = tf32r(v.y * m);
        v.z = tf32r(v.z * m); v.w = tf32r(v.w * m);
        *(float4*)(g_V + (size_t)l * DIMC + j * 4) = v;
    }
}

// ---------------- TF32 flash attention ----------------
// 128 q rows per block, 8 warps (16 rows each), 64-row kv tiles.
#define QPITCH 132
#define VPITCH 136
#define PPITCH 68
#define ATTN_SMEM ((128 * QPITCH + 64 * QPITCH + 64 * VPITCH + 8 * 16 * PPITCH) * 4)

__global__ __launch_bounds__(256) void attn_tf32_kernel(
    const float* __restrict__ Q, const float* __restrict__ K,
    const float* __restrict__ V, float* __restrict__ O) {
    extern __shared__ float sm[];
    float* Qs = sm;                         // [128][QPITCH]
    float* Ks = Qs + 128 * QPITCH;          // [64][QPITCH]
    float* Vs = Ks + 64 * QPITCH;           // [64][VPITCH]
    float* Ps = Vs + 64 * VPITCH;           // [8][16][PPITCH]

    const int qt = blockIdx.x, n = blockIdx.y;
    const int t = threadIdx.x;
    const int w = t >> 5, lane = t & 31, g = lane >> 2, tg = lane & 3;
    const int rb = w * 16;
    float* Pw = Ps + w * 16 * PPITCH;

    // load Q tile [128][128]
#pragma unroll
    for (int u = 0; u < 16; u++) {
        int idx = t + 256 * u;
        int r = idx >> 5, c4 = idx & 31;
        *(float4*)(Qs + r * QPITCH + c4 * 4) =
            *(const float4*)(Q + (size_t)(qt * 128 + r) * DIMC + n * HD + c4 * 4);
    }

    float rm0 = -1e30f, rm1 = -1e30f, rl0 = 0.f, rl1 = 0.f;
    float o[16][4];
#pragma unroll
    for (int nj = 0; nj < 16; nj++)
#pragma unroll
        for (int r = 0; r < 4; r++) o[nj][r] = 0.f;

    const float scale = 0.08838834764831845f;

    for (int kt = 0; kt < LT / 64; kt++) {
        __syncthreads();
#pragma unroll
        for (int u = 0; u < 8; u++) {
            int idx = t + 256 * u;
            int r = idx >> 5, c4 = idx & 31;
            *(float4*)(Ks + r * QPITCH + c4 * 4) =
                *(const float4*)(K + (size_t)(kt * 64 + r) * DIMC + n * HD + c4 * 4);
            *(float4*)(Vs + r * VPITCH + c4 * 4) =
                *(const float4*)(V + (size_t)(kt * 64 + r) * DIMC + n * HD + c4 * 4);
        }
        __syncthreads();

        // S = Q K^T : 16 x 64 per warp
        float s[8][4];
#pragma unroll
        for (int nj = 0; nj < 8; nj++)
#pragma unroll
            for (int r = 0; r < 4; r++) s[nj][r] = 0.f;

#pragma unroll
        for (int kk = 0; kk < 16; kk++) {
            const int k = kk * 8;
            uint32_t a[4];
            a[0] = fbits(Qs[(rb + g) * QPITCH + k + tg]);
            a[1] = fbits(Qs[(rb + g + 8) * QPITCH + k + tg]);
            a[2] = fbits(Qs[(rb + g) * QPITCH + k + tg + 4]);
            a[3] = fbits(Qs[(rb + g + 8) * QPITCH + k + tg + 4]);
#pragma unroll
            for (int nj = 0; nj < 8; nj++) {
                uint32_t b[2];
                b[0] = fbits(Ks[(nj * 8 + g) * QPITCH + k + tg]);
                b[1] = fbits(Ks[(nj * 8 + g) * QPITCH + k + tg + 4]);
                mma_tf32(s[nj], a, b);
            }
        }

        // online softmax (rows g and g+8 of this warp's 16)
        float tm0 = -1e30f, tm1 = -1e30f;
#pragma unroll
        for (int nj = 0; nj < 8; nj++) {
            s[nj][0] *= scale; s[nj][1] *= scale; s[nj][2] *= scale; s[nj][3] *= scale;
            tm0 = fmaxf(tm0, fmaxf(s[nj][0], s[nj][1]));
            tm1 = fmaxf(tm1, fmaxf(s[nj][2], s[nj][3]));
        }
        tm0 = fmaxf(tm0, __shfl_xor_sync(0xffffffffu, tm0, 1));
        tm0 = fmaxf(tm0, __shfl_xor_sync(0xffffffffu, tm0, 2));
        tm1 = fmaxf(tm1, __shfl_xor_sync(0xffffffffu, tm1, 1));
        tm1 = fmaxf(tm1, __shfl_xor_sync(0xffffffffu, tm1, 2));
        float nm0 = fmaxf(rm0, tm0), nm1 = fmaxf(rm1, tm1);
        float corr0 = __expf(rm0 - nm0), corr1 = __expf(rm1 - nm1);

        float ps0 = 0.f, ps1 = 0.f;
#pragma unroll
        for (int nj = 0; nj < 8; nj++) {
            float p0 = __expf(s[nj][0] - nm0);
            float p1 = __expf(s[nj][1] - nm0);
            float p2 = __expf(s[nj][2] - nm1);
            float p3 = __expf(s[nj][3] - nm1);
            ps0 += p0 + p1; ps1 += p2 + p3;
            *(float2*)(Pw + g * PPITCH + nj * 8 + 2 * tg)       = make_float2(tf32r(p0), tf32r(p1));
            *(float2*)(Pw + (g + 8) * PPITCH + nj * 8 + 2 * tg) = make_float2(tf32r(p2), tf32r(p3));
        }
        ps0 += __shfl_xor_sync(0xffffffffu, ps0, 1);
        ps0 += __shfl_xor_sync(0xffffffffu, ps0, 2);
        ps1 += __shfl_xor_sync(0xffffffffu, ps1, 1);
        ps1 += __shfl_xor_sync(0xffffffffu, ps1, 2);
        rl0 = rl0 * corr0 + ps0;
        rl1 = rl1 * corr1 + ps1;
        rm0 = nm0; rm1 = nm1;
#pragma unroll
        for (int nj = 0; nj < 16; nj++) {
            o[nj][0] *= corr0; o[nj][1] *= corr0;
            o[nj][2] *= corr1; o[nj][3] *= corr1;
        }
        __syncwarp();

        // O += P V : P 16x64, V 64x128
#pragma unroll
        for (int kk = 0; kk < 8; kk++) {
            const int k = kk * 8;
            uint32_t a[4];
            a[0] = fbits(Pw[g * PPITCH + k + tg]);
            a[1] = fbits(Pw[(g + 8) * PPITCH + k + tg]);
            a[2] = fbits(Pw[g * PPITCH + k + tg + 4]);
            a[3] = fbits(Pw[(g + 8) * PPITCH + k + tg + 4]);
#pragma unroll
            for (int nj = 0; nj < 16; nj++) {
                uint32_t b[2];
                b[0] = fbits(Vs[(k + tg) * VPITCH + nj * 8 + g]);
                b[1] = fbits(Vs[(k + tg + 4) * VPITCH + nj * 8 + g]);
                mma_tf32(o[nj], a, b);
            }
        }
        __syncwarp();
    }

    // epilogue (round ctx to tf32 for the O-projection GEMM)
    float inv0 = 1.f / rl0, inv1 = 1.f / rl1;
    int row0 = qt * 128 + rb + g;
#pragma unroll
    for (int nj = 0; nj < 16; nj++) {
        int col = n * HD + nj * 8 + 2 * tg;
        *(float2*)(O + (size_t)row0 * DIMC + col) =
            make_float2(tf32r(o[nj][0] * inv0), tf32r(o[nj][1] * inv0));
        *(float2*)(O + (size_t)(row0 + 8) * DIMC + col) =
            make_float2(tf32r(o[nj][2] * inv1), tf32r(o[nj][3] * inv1));
    }
}

// ---------------- launch ----------------
extern "C" void kernel_launch(void* const* d_in, const int* in_sizes, int n_in,
                              void* d_out, int out_size) {
    const float* x    = (const float*)d_in[0];
    const float* Wq   = (const float*)d_in[1];
    const float* bq   = (const float*)d_in[2];
    const float* Wk   = (const float*)d_in[3];
    const float* bk   = (const float*)d_in[4];
    const float* Wv   = (const float*)d_in[5];
    const float* bv   = (const float*)d_in[6];
    const float* Wo   = (const float*)d_in[7];
    const float* bo   = (const float*)d_in[8];
    const float* wqn  = (const float*)d_in[9];
    const float* wkn  = (const float*)d_in[10];
    const float* pk   = (const float*)d_in[11];
    const float* pv   = (const float*)d_in[12];
    const float* fcos = (const float*)d_in[13];
    const float* fsin = (const float*)d_in[14];
    const int*   hm   = (const int*)d_in[15];
    const int*   shift = (const int*)d_in[18];
    float* out = (float*)d_out;

    float *qraw, *kraw, *q, *K, *V, *ctx, *xr, *Wqr, *Wkr, *Wvr, *Wor;
    cudaGetSymbolAddress((void**)&qraw, g_qraw);
    cudaGetSymbolAddress((void**)&kraw, g_kraw);
    cudaGetSymbolAddress((void**)&q,    g_q);
    cudaGetSymbolAddress((void**)&K,    g_K);
    cudaGetSymbolAddress((void**)&V,    g_V);
    cudaGetSymbolAddress((void**)&ctx,  g_ctx);
    cudaGetSymbolAddress((void**)&xr,   g_xr);
    cudaGetSymbolAddress((void**)&Wqr,  g_Wqr);
    cudaGetSymbolAddress((void**)&Wkr,  g_Wkr);
    cudaGetSymbolAddress((void**)&Wvr,  g_Wvr);
    cudaGetSymbolAddress((void**)&Wor,  g_Wor);

    // round inputs to tf32 once
    {
        int n4 = Sq * DIMC / 4;
        round_tf32_kernel<<<(n4 + 255) / 256, 256>>>(x, xr, n4);
        int w4 = DIMC * DIMC / 4;
        round_tf32_kernel<<<(w4 + 255) / 256, 256>>>(Wq, Wqr, w4);
        round_tf32_kernel<<<(w4 + 255) / 256, 256>>>(Wk, Wkr, w4);
        round_tf32_kernel<<<(w4 + 255) / 256, 256>>>(Wv, Wvr, w4);
        round_tf32_kernel<<<(w4 + 255) / 256, 256>>>(Wo, Wor, w4);
    }

    cudaFuncSetAttribute(tf32_gemm_kernel, cudaFuncAttributeMaxDynamicSharedMemorySize, GEMM_SMEM);
    cudaFuncSetAttribute(attn_tf32_kernel, cudaFuncAttributeMaxDynamicSharedMemorySize, ATTN_SMEM);

    dim3 ggrid(DIMC / GBN, Sq / GBM);
    tf32_gemm_kernel<<<ggrid, 256, GEMM_SMEM>>>(xr, Wqr, bq, qraw, 0);
    tf32_gemm_kernel<<<ggrid, 256, GEMM_SMEM>>>(xr, Wkr, bk, kraw, 0);
    tf32_gemm_kernel<<<ggrid, 256, GEMM_SMEM>>>(xr, Wvr, bv, V + (size_t)LC * DIMC, 1);

    norm_rope_kernel<<<Sq, 256>>>(qraw, wqn, fcos, fsin, q);
    norm_rope_kernel<<<Sq, 256>>>(kraw, wkn, fcos, fsin, K + (size_t)LC * DIMC);

    cache_prep_kernel<<<LC, 256>>>(pk, pv, fcos, fsin, hm, shift);

    attn_tf32_kernel<<<dim3(Sq / 128, NH), 256, ATTN_SMEM>>>(q, K, V, ctx);

    tf32_gemm_kernel<<<ggrid, 256, GEMM_SMEM>>>(ctx, Wor, bo, out, 0);
}

// round 6
// speedup vs baseline: 8.3072x; 2.2208x over previous
#include <cuda_runtime.h>
#include <cuda_fp16.h>
#include <math.h>
#include <stdint.h>

// ---------------- constants ----------------
#define Sq   3072
#define LC   768
#define LT   3840
#define DIMC 1536
#define NH   12
#define HD   128
#define CP   64
#define C0P  22
#define C1P  21
#define WW   24
#define HW   384

// ---------------- scratch ----------------
__device__ float  g_qraw[Sq * DIMC];
__device__ float  g_kraw[Sq * DIMC];
__device__ __half g_xh[Sq * DIMC];
__device__ __half g_q[Sq * DIMC];
__device__ __half g_K[LT * DIMC];
__device__ __half g_V[LT * DIMC];
__device__ __half g_ctx[Sq * DIMC];
__device__ __half g_WqT[DIMC * DIMC];
__device__ __half g_WkT[DIMC * DIMC];
__device__ __half g_WvT[DIMC * DIMC];
__device__ __half g_WoT[DIMC * DIMC];

// ---------------- helpers ----------------
__device__ __forceinline__ uint32_t smem_u32(const void* p) {
    return (uint32_t)__cvta_generic_to_shared(p);
}
__device__ __forceinline__ void cpa16(void* s, const void* g) {
    uint32_t sa = (uint32_t)__cvta_generic_to_shared(s);
    asm volatile("cp.async.cg.shared.global [%0], [%1], 16;" :: "r"(sa), "l"(g));
}
#define CP_COMMIT() asm volatile("cp.async.commit_group;")
#define CP_WAIT0()  asm volatile("cp.async.wait_group 0;")

#define LDSM4(r0, r1, r2, r3, addr) \
    asm volatile("ldmatrix.sync.aligned.m8n8.x4.shared.b16 {%0,%1,%2,%3}, [%4];" \
                 : "=r"(r0), "=r"(r1), "=r"(r2), "=r"(r3) : "r"(addr))
#define LDSM4T(r0, r1, r2, r3, addr) \
    asm volatile("ldmatrix.sync.aligned.m8n8.x4.trans.shared.b16 {%0,%1,%2,%3}, [%4];" \
                 : "=r"(r0), "=r"(r1), "=r"(r2), "=r"(r3) : "r"(addr))

__device__ __forceinline__ void mma_f16(float* d, const uint32_t* a, const uint32_t* b) {
    asm volatile(
        "mma.sync.aligned.m16n8k16.row.col.f32.f16.f16.f32 "
        "{%0,%1,%2,%3}, {%4,%5,%6,%7}, {%8,%9}, {%0,%1,%2,%3};\n"
        : "+f"(d[0]), "+f"(d[1]), "+f"(d[2]), "+f"(d[3])
        : "r"(a[0]), "r"(a[1]), "r"(a[2]), "r"(a[3]), "r"(b[0]), "r"(b[1]));
}

__device__ __forceinline__ uint32_t packh2(float lo, float hi) {
    __half2 h = __floats2half2_rn(lo, hi);
    return *(uint32_t*)&h;
}

// ---------------- f32 -> f16 convert ----------------
__global__ void f2h_kernel(const float* __restrict__ in, __half* __restrict__ out, int n4) {
    int i = blockIdx.x * blockDim.x + threadIdx.x;
    if (i < n4) {
        float4 v = ((const float4*)in)[i];
        uint2 o;
        o.x = packh2(v.x, v.y);
        o.y = packh2(v.z, v.w);
        ((uint2*)out)[i] = o;
    }
}

// WT[n,k] = f16(W[k,n])
__global__ void wtrans_kernel(const float* __restrict__ W, __half* __restrict__ WT) {
    __shared__ float tile[32][33];
    int n0 = blockIdx.x * 32, k0 = blockIdx.y * 32;
    int x = threadIdx.x, y = threadIdx.y;  // 32 x 8
    for (int yy = y; yy < 32; yy += 8)
        tile[yy][x] = W[(size_t)(k0 + yy) * DIMC + n0 + x];
    __syncthreads();
    for (int yy = y; yy < 32; yy += 8)
        WT[(size_t)(n0 + yy) * DIMC + k0 + x] = __float2half_rn(tile[x][yy]);
}

// ---------------- FP16 GEMM: C[3072,1536] = A @ BT^T + bias ----------------
// A [M,K] f16 row-major, BT [N,K] f16 row-major. Tile 128x128, k-chunk 64.
#define BM  128
#define BN  128
#define BKH 64          // halves per chunk
#define KP  144         // bytes per smem row (72 halves)
#define ABUFB (BM * KP) // 18432
#define GSMEM (4 * ABUFB)

template <int OUTHALF>
__global__ __launch_bounds__(256) void hgemm_kernel(
    const __half* __restrict__ A, const __half* __restrict__ BT,
    const float* __restrict__ bias, void* __restrict__ Cout) {
    extern __shared__ __align__(1024) char smem[];
    const uint32_t sb = smem_u32(smem);
    const int t = threadIdx.x, w = t >> 5, lane = t & 31, g = lane >> 2, tg = lane & 3;
    const int wm = w >> 1, wn = w & 1;
    const int row0 = blockIdx.y * BM, col0 = blockIdx.x * BN;
    const int lr = t >> 3, lc = t & 7;

    float acc[2][8][4];
#pragma unroll
    for (int mi = 0; mi < 2; mi++)
#pragma unroll
        for (int nj = 0; nj < 8; nj++)
#pragma unroll
            for (int r = 0; r < 4; r++) acc[mi][nj][r] = 0.f;

    auto load_chunk = [&](int k0, int buf) {
#pragma unroll
        for (int u = 0; u < 4; u++) {
            int r = lr + u * 32;
            cpa16(smem + buf * ABUFB + r * KP + lc * 16,
                  A + (size_t)(row0 + r) * DIMC + k0 + lc * 8);
            cpa16(smem + 2 * ABUFB + buf * ABUFB + r * KP + lc * 16,
                  BT + (size_t)(col0 + r) * DIMC + k0 + lc * 8);
        }
    };

    load_chunk(0, 0);
    CP_COMMIT();

    const uint32_t aAddr = sb + (wm * 32 + (lane & 15)) * KP + (lane >> 4) * 16;
    const uint32_t bAddr = sb + 2 * ABUFB +
        (wn * 64 + ((lane >> 4) << 3) + (lane & 7)) * KP + ((lane >> 3) & 1) * 16;

    const int NCH = DIMC / BKH;   // 24
    for (int i = 0; i < NCH; i++) {
        CP_WAIT0();
        __syncthreads();
        if (i + 1 < NCH) load_chunk((i + 1) * BKH, (i + 1) & 1);
        CP_COMMIT();

        const uint32_t ab = aAddr + (i & 1) * ABUFB;
        const uint32_t bb = bAddr + (i & 1) * ABUFB;
#pragma unroll
        for (int ks = 0; ks < 4; ks++) {
            uint32_t a[2][4];
            LDSM4(a[0][0], a[0][1], a[0][2], a[0][3], ab + ks * 32);
            LDSM4(a[1][0], a[1][1], a[1][2], a[1][3], ab + 16 * KP + ks * 32);
            uint32_t b[8][2];
#pragma unroll
            for (int njp = 0; njp < 4; njp++)
                LDSM4(b[2 * njp][0], b[2 * njp][1], b[2 * njp + 1][0], b[2 * njp + 1][1],
                      bb + njp * 16 * KP + ks * 32);
#pragma unroll
            for (int mi = 0; mi < 2; mi++)
#pragma unroll
                for (int nj = 0; nj < 8; nj++) mma_f16(acc[mi][nj], a[mi], b[nj]);
        }
    }

    float* Cf = (float*)Cout;
    __half* Ch = (__half*)Cout;
#pragma unroll
    for (int mi = 0; mi < 2; mi++) {
#pragma unroll
        for (int hf = 0; hf < 2; hf++) {
            int row = row0 + wm * 32 + mi * 16 + g + hf * 8;
#pragma unroll
            for (int nj = 0; nj < 8; nj++) {
                int col = col0 + wn * 64 + nj * 8 + 2 * tg;
                float v0 = acc[mi][nj][hf * 2 + 0] + bias[col];
                float v1 = acc[mi][nj][hf * 2 + 1] + bias[col + 1];
                if (OUTHALF) {
                    __half2 hv = __floats2half2_rn(v0, v1);
                    *(__half2*)(Ch + (size_t)row * DIMC + col) = hv;
                } else {
                    *(float2*)(Cf + (size_t)row * DIMC + col) = make_float2(v0, v1);
                }
            }
        }
    }
}

// ---------------- RMSNorm + RoPE -> f16 ----------------
__inline__ __device__ float block_reduce_sum(float v) {
    __shared__ float red[8];
#pragma unroll
    for (int o = 16; o > 0; o >>= 1) v += __shfl_xor_sync(0xffffffffu, v, o);
    int wid = threadIdx.x >> 5, lane = threadIdx.x & 31;
    if (lane == 0) red[wid] = v;
    __syncthreads();
    if (wid == 0) {
        v = (lane < 8) ? red[lane] : 0.f;
#pragma unroll
        for (int o = 4; o > 0; o >>= 1) v += __shfl_xor_sync(0xffffffffu, v, o);
        if (lane == 0) red[0] = v;
    }
    __syncthreads();
    return red[0];
}

__global__ void norm_rope_kernel(const float* __restrict__ in,
                                 const float* __restrict__ w,
                                 const float* __restrict__ fcos,
                                 const float* __restrict__ fsin,
                                 __half* __restrict__ out) {
    const int s = blockIdx.x;
    const int t = threadIdx.x;
    const float* row = in + (size_t)s * DIMC;

    float ss = 0.f;
    for (int j = t; j < DIMC / 4; j += 256) {
        float4 v = *(const float4*)(row + j * 4);
        ss += v.x * v.x + v.y * v.y + v.z * v.z + v.w * v.w;
    }
    ss = block_reduce_sum(ss);
    const float scale = rsqrtf(ss * (1.0f / DIMC) + 1e-6f);

    const int f = s / HW;
    const int rem = s - f * HW;
    const int h = rem / WW;
    const int wp = rem - h * WW;

    __half2* out2 = (__half2*)(out + (size_t)s * DIMC);
    for (int p = t; p < DIMC / 2; p += 256) {
        int c = p & (CP - 1);
        int pos = (c < C0P) ? f : (c < C0P + C1P) ? h : wp;
        float fc = fcos[pos * CP + c];
        float fs = fsin[pos * CP + c];
        float a = row[2 * p] * scale * w[2 * p];
        float b = row[2 * p + 1] * scale * w[2 * p + 1];
        out2[p] = __floats2half2_rn(a * fc - b * fs, a * fs + b * fc);
    }
}

// ---------------- cache prep -> f16 ----------------
__global__ void cache_prep_kernel(const float* __restrict__ pk,
                                  const float* __restrict__ pv,
                                  const float* __restrict__ fcos,
                                  const float* __restrict__ fsin,
                                  const int* __restrict__ hm,
                                  const int* __restrict__ shift_ptr) {
    const int l = blockIdx.x;
    const int t = threadIdx.x;
    const int shift = *shift_ptr;

    const int f = l / HW;
    const int rem = l - f * HW;
    const int h = rem / WW;
    const int wp = rem - h * WW;

    __half2* K2 = (__half2*)(g_K + (size_t)l * DIMC);
    __half2* V2 = (__half2*)(g_V + (size_t)l * DIMC);

    for (int p = t; p < DIMC / 2; p += 256) {
        int n = p >> 6;
        int c = p & (CP - 1);
        float m = (hm[n] != 0) ? 1.f : 0.f;
        int pos = (c < C0P) ? (shift + f) : (c < C0P + C1P) ? h : wp;
        float fc = fcos[pos * CP + c];
        float fs = fsin[pos * CP + c];
        float a = pk[(size_t)l * DIMC + 2 * p];
        float b = pk[(size_t)l * DIMC + 2 * p + 1];
        K2[p] = __floats2half2_rn((a * fc - b * fs) * m, (a * fs + b * fc) * m);
    }
    for (int j = t; j < DIMC / 4; j += 256) {
        float4 v = *(const float4*)(pv + (size_t)l * DIMC + j * 4);
        int n = (j * 4) >> 7;
        float m = (hm[n] != 0) ? 1.f : 0.f;
        V2[2 * j]     = __floats2half2_rn(v.x * m, v.y * m);
        V2[2 * j + 1] = __floats2half2_rn(v.z * m, v.w * m);
    }
}

// ---------------- FP16 flash attention ----------------
// 128 q rows / CTA, 8 warps (16 rows each), 64-key kv tiles, double-buffered.
#define QP    272                 // bytes per smem row (136 halves)
#define QBYT  (128 * QP)          // 34816
#define KOFF  QBYT
#define TILEB (64 * QP)           // 17408
#define VOFF  (KOFF + 2 * TILEB)
#define ASMEM (VOFF + 2 * TILEB)  // 104448

__global__ __launch_bounds__(256) void attn_h_kernel(
    const __half* __restrict__ Q, const __half* __restrict__ K,
    const __half* __restrict__ V, __half* __restrict__ O) {
    extern __shared__ __align__(1024) char smem[];
    const uint32_t sb = smem_u32(smem);
    const int qt = blockIdx.x, hN = blockIdx.y;
    const int t = threadIdx.x, w = t >> 5, lane = t & 31, g = lane >> 2, tg = lane & 3;
    const int rb = w * 16;

    // Q tile load
#pragma unroll
    for (int u = 0; u < 8; u++) {
        int id = t + u * 256;
        int r = id >> 4, c = id & 15;
        cpa16(smem + r * QP + c * 16, Q + (size_t)(qt * 128 + r) * DIMC + hN * HD + c * 8);
    }
    auto load_tile = [&](int kt, int buf) {
#pragma unroll
        for (int u = 0; u < 4; u++) {
            int id = t + u * 256;
            int r = id >> 4, c = id & 15;
            cpa16(smem + KOFF + buf * TILEB + r * QP + c * 16,
                  K + (size_t)(kt * 64 + r) * DIMC + hN * HD + c * 8);
            cpa16(smem + VOFF + buf * TILEB + r * QP + c * 16,
                  V + (size_t)(kt * 64 + r) * DIMC + hN * HD + c * 8);
        }
    };
    load_tile(0, 0);
    CP_COMMIT();

    const uint32_t qAddr = sb + (rb + (lane & 15)) * QP + (lane >> 4) * 16;
    const uint32_t kAddr = sb + KOFF + (((lane >> 4) << 3) + (lane & 7)) * QP + ((lane >> 3) & 1) * 16;
    const uint32_t vAddr = sb + VOFF + (lane & 15) * QP + (lane >> 4) * 16;

    float rm0 = -1e30f, rm1 = -1e30f, rl0 = 0.f, rl1 = 0.f;
    float o[16][4];
#pragma unroll
    for (int nj = 0; nj < 16; nj++)
#pragma unroll
        for (int r = 0; r < 4; r++) o[nj][r] = 0.f;

    const float scale = 0.08838834764831845f;

    for (int kt = 0; kt < LT / 64; kt++) {
        CP_WAIT0();
        __syncthreads();
        if (kt + 1 < LT / 64) load_tile(kt + 1, (kt + 1) & 1);
        CP_COMMIT();

        const uint32_t kb = kAddr + (kt & 1) * TILEB;
        const uint32_t vb = vAddr + (kt & 1) * TILEB;

        // S = Q K^T  (16 x 64 per warp)
        float s[8][4];
#pragma unroll
        for (int nj = 0; nj < 8; nj++)
#pragma unroll
            for (int r = 0; r < 4; r++) s[nj][r] = 0.f;

#pragma unroll
        for (int ks = 0; ks < 8; ks++) {
            uint32_t a[4];
            LDSM4(a[0], a[1], a[2], a[3], qAddr + ks * 32);
#pragma unroll
            for (int njp = 0; njp < 4; njp++) {
                uint32_t b[4];
                LDSM4(b[0], b[1], b[2], b[3], kb + njp * 16 * QP + ks * 32);
                mma_f16(s[2 * njp], a, b);
                mma_f16(s[2 * njp + 1], a, b + 2);
            }
        }

        // online softmax (rows g / g+8)
        float tm0 = -1e30f, tm1 = -1e30f;
#pragma unroll
        for (int nj = 0; nj < 8; nj++) {
            s[nj][0] *= scale; s[nj][1] *= scale; s[nj][2] *= scale; s[nj][3] *= scale;
            tm0 = fmaxf(tm0, fmaxf(s[nj][0], s[nj][1]));
            tm1 = fmaxf(tm1, fmaxf(s[nj][2], s[nj][3]));
        }
        tm0 = fmaxf(tm0, __shfl_xor_sync(0xffffffffu, tm0, 1));
        tm0 = fmaxf(tm0, __shfl_xor_sync(0xffffffffu, tm0, 2));
        tm1 = fmaxf(tm1, __shfl_xor_sync(0xffffffffu, tm1, 1));
        tm1 = fmaxf(tm1, __shfl_xor_sync(0xffffffffu, tm1, 2));
        float nm0 = fmaxf(rm0, tm0), nm1 = fmaxf(rm1, tm1);
        float corr0 = __expf(rm0 - nm0), corr1 = __expf(rm1 - nm1);

        float pf[8][4];
        float ps0 = 0.f, ps1 = 0.f;
#pragma unroll
        for (int nj = 0; nj < 8; nj++) {
            pf[nj][0] = __expf(s[nj][0] - nm0);
            pf[nj][1] = __expf(s[nj][1] - nm0);
            pf[nj][2] = __expf(s[nj][2] - nm1);
            pf[nj][3] = __expf(s[nj][3] - nm1);
            ps0 += pf[nj][0] + pf[nj][1];
            ps1 += pf[nj][2] + pf[nj][3];
        }
        ps0 += __shfl_xor_sync(0xffffffffu, ps0, 1);
        ps0 += __shfl_xor_sync(0xffffffffu, ps0, 2);
        ps1 += __shfl_xor_sync(0xffffffffu, ps1, 1);
        ps1 += __shfl_xor_sync(0xffffffffu, ps1, 2);
        rl0 = rl0 * corr0 + ps0;
        rl1 = rl1 * corr1 + ps1;
        rm0 = nm0; rm1 = nm1;

        // P: C-fragments -> fp16 A-fragments, in registers
        uint32_t pa[4][4];
#pragma unroll
        for (int kk = 0; kk < 4; kk++) {
            pa[kk][0] = packh2(pf[2 * kk][0],     pf[2 * kk][1]);
            pa[kk][1] = packh2(pf[2 * kk][2],     pf[2 * kk][3]);
            pa[kk][2] = packh2(pf[2 * kk + 1][0], pf[2 * kk + 1][1]);
            pa[kk][3] = packh2(pf[2 * kk + 1][2], pf[2 * kk + 1][3]);
        }

#pragma unroll
        for (int nj = 0; nj < 16; nj++) {
            o[nj][0] *= corr0; o[nj][1] *= corr0;
            o[nj][2] *= corr1; o[nj][3] *= corr1;
        }

        // O += P V  (V via ldmatrix.trans)
#pragma unroll
        for (int kk = 0; kk < 4; kk++) {
#pragma unroll
            for (int njp = 0; njp < 8; njp++) {
                uint32_t b[4];
                LDSM4T(b[0], b[1], b[2], b[3], vb + kk * 16 * QP + njp * 32);
                mma_f16(o[2 * njp], pa[kk], b);
                mma_f16(o[2 * njp + 1], pa[kk], b + 2);
            }
        }
    }

    // epilogue -> f16 ctx
    float inv0 = 1.f / rl0, inv1 = 1.f / rl1;
    int row0 = qt * 128 + rb + g;
#pragma unroll
    for (int nj = 0; nj < 16; nj++) {
        int col = hN * HD + nj * 8 + 2 * tg;
        *(__half2*)(O + (size_t)row0 * DIMC + col) =
            __floats2half2_rn(o[nj][0] * inv0, o[nj][1] * inv0);
        *(__half2*)(O + (size_t)(row0 + 8) * DIMC + col) =
            __floats2half2_rn(o[nj][2] * inv1, o[nj][3] * inv1);
    }
}

// ---------------- launch ----------------
extern "C" void kernel_launch(void* const* d_in, const int* in_sizes, int n_in,
                              void* d_out, int out_size) {
    const float* x    = (const float*)d_in[0];
    const float* Wq   = (const float*)d_in[1];
    const float* bq   = (const float*)d_in[2];
    const float* Wk   = (const float*)d_in[3];
    const float* bk   = (const float*)d_in[4];
    const float* Wv   = (const float*)d_in[5];
    const float* bv   = (const float*)d_in[6];
    const float* Wo   = (const float*)d_in[7];
    const float* bo   = (const float*)d_in[8];
    const float* wqn  = (const float*)d_in[9];
    const float* wkn  = (const float*)d_in[10];
    const float* pk   = (const float*)d_in[11];
    const float* pv   = (const float*)d_in[12];
    const float* fcos = (const float*)d_in[13];
    const float* fsin = (const float*)d_in[14];
    const int*   hm   = (const int*)d_in[15];
    const int*   shift = (const int*)d_in[18];
    float* out = (float*)d_out;

    float *qraw, *kraw;
    __half *xh, *q, *Kh, *Vh, *ctx, *WqT, *WkT, *WvT, *WoT;
    cudaGetSymbolAddress((void**)&qraw, g_qraw);
    cudaGetSymbolAddress((void**)&kraw, g_kraw);
    cudaGetSymbolAddress((void**)&xh,   g_xh);
    cudaGetSymbolAddress((void**)&q,    g_q);
    cudaGetSymbolAddress((void**)&Kh,   g_K);
    cudaGetSymbolAddress((void**)&Vh,   g_V);
    cudaGetSymbolAddress((void**)&ctx,  g_ctx);
    cudaGetSymbolAddress((void**)&WqT,  g_WqT);
    cudaGetSymbolAddress((void**)&WkT,  g_WkT);
    cudaGetSymbolAddress((void**)&WvT,  g_WvT);
    cudaGetSymbolAddress((void**)&WoT,  g_WoT);

    // convert x; transpose+convert weights
    {
        int n4 = Sq * DIMC / 4;
        f2h_kernel<<<(n4 + 255) / 256, 256>>>(x, xh, n4);
        dim3 tg(DIMC / 32, DIMC / 32), tb(32, 8);
        wtrans_kernel<<<tg, tb>>>(Wq, WqT);
        wtrans_kernel<<<tg, tb>>>(Wk, WkT);
        wtrans_kernel<<<tg, tb>>>(Wv, WvT);
        wtrans_kernel<<<tg, tb>>>(Wo, WoT);
    }

    cudaFuncSetAttribute(hgemm_kernel<0>, cudaFuncAttributeMaxDynamicSharedMemorySize, GSMEM);
    cudaFuncSetAttribute(hgemm_kernel<1>, cudaFuncAttributeMaxDynamicSharedMemorySize, GSMEM);
    cudaFuncSetAttribute(attn_h_kernel, cudaFuncAttributeMaxDynamicSharedMemorySize, ASMEM);

    dim3 ggrid(DIMC / BN, Sq / BM);   // (12, 24)
    hgemm_kernel<0><<<ggrid, 256, GSMEM>>>(xh, WqT, bq, qraw);
    hgemm_kernel<0><<<ggrid, 256, GSMEM>>>(xh, WkT, bk, kraw);
    hgemm_kernel<1><<<ggrid, 256, GSMEM>>>(xh, WvT, bv, Vh + (size_t)LC * DIMC);

    norm_rope_kernel<<<Sq, 256>>>(qraw, wqn, fcos, fsin, q);
    norm_rope_kernel<<<Sq, 256>>>(kraw, wkn, fcos, fsin, Kh + (size_t)LC * DIMC);

    cache_prep_kernel<<<LC, 256>>>(pk, pv, fcos, fsin, hm, shift);

    attn_h_kernel<<<dim3(Sq / 128, NH), 256, ASMEM>>>(q, Kh, Vh, ctx);

    hgemm_kernel<0><<<ggrid, 256, GSMEM>>>(ctx, WoT, bo, out);
}

// round 7
// speedup vs baseline: 8.3263x; 1.0023x over previous
#include <cuda_runtime.h>
#include <cuda_fp16.h>
#include <math.h>
#include <stdint.h>

// ---------------- constants ----------------
#define Sq   3072
#define LC   768
#define LT   3840
#define DIMC 1536
#define NH   12
#define HD   128
#define CP   64
#define C0P  22
#define C1P  21
#define WW   24
#define HW   384

// ---------------- scratch ----------------
__device__ float  g_qraw[Sq * DIMC];
__device__ float  g_kraw[Sq * DIMC];
__device__ __half g_xh[Sq * DIMC];
__device__ __half g_q[Sq * DIMC];
__device__ __half g_K[LT * DIMC];
__device__ __half g_V[LT * DIMC];
__device__ __half g_ctx[Sq * DIMC];
__device__ __half g_WqkvT[3 * DIMC * DIMC];
__device__ __half g_WoT[DIMC * DIMC];

// ---------------- helpers ----------------
__device__ __forceinline__ uint32_t smem_u32(const void* p) {
    return (uint32_t)__cvta_generic_to_shared(p);
}
__device__ __forceinline__ void cpa16(void* s, const void* g) {
    uint32_t sa = (uint32_t)__cvta_generic_to_shared(s);
    asm volatile("cp.async.cg.shared.global [%0], [%1], 16;" :: "r"(sa), "l"(g));
}
#define CP_COMMIT() asm volatile("cp.async.commit_group;")
#define CP_WAIT1()  asm volatile("cp.async.wait_group 1;")

#define LDSM4(r0, r1, r2, r3, addr) \
    asm volatile("ldmatrix.sync.aligned.m8n8.x4.shared.b16 {%0,%1,%2,%3}, [%4];" \
                 : "=r"(r0), "=r"(r1), "=r"(r2), "=r"(r3) : "r"(addr))
#define LDSM4T(r0, r1, r2, r3, addr) \
    asm volatile("ldmatrix.sync.aligned.m8n8.x4.trans.shared.b16 {%0,%1,%2,%3}, [%4];" \
                 : "=r"(r0), "=r"(r1), "=r"(r2), "=r"(r3) : "r"(addr))

__device__ __forceinline__ void mma_f16(float* d, const uint32_t* a, const uint32_t* b) {
    asm volatile(
        "mma.sync.aligned.m16n8k16.row.col.f32.f16.f16.f32 "
        "{%0,%1,%2,%3}, {%4,%5,%6,%7}, {%8,%9}, {%0,%1,%2,%3};\n"
        : "+f"(d[0]), "+f"(d[1]), "+f"(d[2]), "+f"(d[3])
        : "r"(a[0]), "r"(a[1]), "r"(a[2]), "r"(a[3]), "r"(b[0]), "r"(b[1]));
}
__device__ __forceinline__ uint32_t packh2(float lo, float hi) {
    __half2 h = __floats2half2_rn(lo, hi);
    return *(uint32_t*)&h;
}

// ---------------- prep: f32 -> f16 ----------------
__global__ void f2h_kernel(const float* __restrict__ in, __half* __restrict__ out, int n4) {
    int i = blockIdx.x * blockDim.x + threadIdx.x;
    if (i < n4) {
        float4 v = ((const float4*)in)[i];
        uint2 o;
        o.x = packh2(v.x, v.y);
        o.y = packh2(v.z, v.w);
        ((uint2*)out)[i] = o;
    }
}

// transpose all 4 weights: z<3 -> WqkvT rows z*DIMC.., z==3 -> WoT
__global__ void wtrans_all_kernel(const float* __restrict__ W0, const float* __restrict__ W1,
                                  const float* __restrict__ W2, const float* __restrict__ W3) {
    __shared__ float tile[32][33];
    const float* W = (blockIdx.z == 0) ? W0 : (blockIdx.z == 1) ? W1 : (blockIdx.z == 2) ? W2 : W3;
    __half* dst = (blockIdx.z < 3) ? (g_WqkvT + (size_t)blockIdx.z * DIMC * DIMC) : g_WoT;
    int n0 = blockIdx.x * 32, k0 = blockIdx.y * 32;
    int x = threadIdx.x, y = threadIdx.y;  // 32 x 8
    for (int yy = y; yy < 32; yy += 8)
        tile[yy][x] = W[(size_t)(k0 + yy) * DIMC + n0 + x];
    __syncthreads();
    for (int yy = y; yy < 32; yy += 8)
        dst[(size_t)(n0 + yy) * DIMC + k0 + x] = __float2half_rn(tile[x][yy]);
}

// ---------------- FP16 GEMM core tiles ----------------
#define BM  128
#define BN  128
#define BKH 64          // halves per k-chunk
#define KP  144         // bytes per smem row (72 halves)
#define ABUFB (BM * KP) // 18432
#define GSMEM (6 * ABUFB)
#define NCH (DIMC / BKH)  // 24

// shared mainloop: returns acc for a 128x128 tile at (row0 of A, brow0 of BT)
template <typename EPI>
__device__ __forceinline__ void hgemm_tile(
    const __half* A, const __half* BT, int row0, int brow0,
    char* smem, EPI epi) {
    const uint32_t sb = smem_u32(smem);
    const int t = threadIdx.x, w = t >> 5, lane = t & 31;
    const int wm = w >> 1, wn = w & 1;
    const int lr = t >> 3, lc = t & 7;

    float acc[2][8][4];
#pragma unroll
    for (int mi = 0; mi < 2; mi++)
#pragma unroll
        for (int nj = 0; nj < 8; nj++)
#pragma unroll
            for (int r = 0; r < 4; r++) acc[mi][nj][r] = 0.f;

    auto load_chunk = [&](int k0, int buf) {
#pragma unroll
        for (int u = 0; u < 4; u++) {
            int r = lr + u * 32;
            cpa16(smem + buf * ABUFB + r * KP + lc * 16,
                  A + (size_t)(row0 + r) * DIMC + k0 + lc * 8);
            cpa16(smem + 3 * ABUFB + buf * ABUFB + r * KP + lc * 16,
                  BT + (size_t)(brow0 + r) * DIMC + k0 + lc * 8);
        }
    };

    load_chunk(0, 0); CP_COMMIT();
    load_chunk(BKH, 1); CP_COMMIT();

    const uint32_t aAddr = sb + (wm * 32 + (lane & 15)) * KP + (lane >> 4) * 16;
    const uint32_t bAddr = sb + 3 * ABUFB +
        (wn * 64 + ((lane >> 4) << 3) + (lane & 7)) * KP + ((lane >> 3) & 1) * 16;

    int cbuf = 0, lbuf = 2;
    for (int i = 0; i < NCH; i++) {
        CP_WAIT1();
        __syncthreads();
        if (i + 2 < NCH) load_chunk((i + 2) * BKH, lbuf);
        CP_COMMIT();

        const uint32_t ab = aAddr + cbuf * ABUFB;
        const uint32_t bb = bAddr + cbuf * ABUFB;
#pragma unroll
        for (int ks = 0; ks < 4; ks++) {
            uint32_t a[2][4];
            LDSM4(a[0][0], a[0][1], a[0][2], a[0][3], ab + ks * 32);
            LDSM4(a[1][0], a[1][1], a[1][2], a[1][3], ab + 16 * KP + ks * 32);
            uint32_t b[8][2];
#pragma unroll
            for (int njp = 0; njp < 4; njp++)
                LDSM4(b[2 * njp][0], b[2 * njp][1], b[2 * njp + 1][0], b[2 * njp + 1][1],
                      bb + njp * 16 * KP + ks * 32);
#pragma unroll
            for (int mi = 0; mi < 2; mi++)
#pragma unroll
                for (int nj = 0; nj < 8; nj++) mma_f16(acc[mi][nj], a[mi], b[nj]);
        }
        cbuf = (cbuf == 2) ? 0 : cbuf + 1;
        lbuf = (lbuf == 2) ? 0 : lbuf + 1;
    }

    // epilogue: epi(row_local, col_local, v0, v1)
#pragma unroll
    for (int mi = 0; mi < 2; mi++) {
#pragma unroll
        for (int hf = 0; hf < 2; hf++) {
            int rl = wm * 32 + mi * 16 + (lane >> 2) + hf * 8;
#pragma unroll
            for (int nj = 0; nj < 8; nj++) {
                int cl = wn * 64 + nj * 8 + 2 * (lane & 3);
                epi(rl, cl, acc[mi][nj][hf * 2 + 0], acc[mi][nj][hf * 2 + 1]);
            }
        }
    }
}

// fused QKV: grid (36, 24). bx/12 selects segment.
__global__ __launch_bounds__(256) void hgemm_qkv_kernel(
    const __half* __restrict__ xh,
    const float* __restrict__ bq, const float* __restrict__ bk, const float* __restrict__ bv) {
    extern __shared__ __align__(1024) char smem[];
    const int bx = blockIdx.x, by = blockIdx.y;
    const int seg = bx / 12, bxl = bx - seg * 12;
    const int row0 = by * BM;
    const int col0 = bxl * BN;
    const float* bias = (seg == 0) ? bq : (seg == 1) ? bk : bv;

    hgemm_tile(xh, g_WqkvT, row0, bx * BN, smem,
        [&](int rl, int cl, float v0, float v1) {
            int row = row0 + rl, col = col0 + cl;
            v0 += bias[col]; v1 += bias[col + 1];
            if (seg == 0) {
                *(float2*)(g_qraw + (size_t)row * DIMC + col) = make_float2(v0, v1);
            } else if (seg == 1) {
                *(float2*)(g_kraw + (size_t)row * DIMC + col) = make_float2(v0, v1);
            } else {
                *(__half2*)(g_V + (size_t)(LC + row) * DIMC + col) = __floats2half2_rn(v0, v1);
            }
        });
}

// O projection: grid (12, 24), float out
__global__ __launch_bounds__(256) void hgemm_o_kernel(
    const float* __restrict__ bo, float* __restrict__ out) {
    extern __shared__ __align__(1024) char smem[];
    const int row0 = blockIdx.y * BM, col0 = blockIdx.x * BN;
    hgemm_tile(g_ctx, g_WoT, row0, col0, smem,
        [&](int rl, int cl, float v0, float v1) {
            int row = row0 + rl, col = col0 + cl;
            *(float2*)(out + (size_t)row * DIMC + col) =
                make_float2(v0 + bo[col], v1 + bo[col + 1]);
        });
}

// ---------------- fused prep: norm_rope(q), norm_rope(k), cache ----------------
__inline__ __device__ float block_reduce_sum(float v) {
    __shared__ float red[8];
#pragma unroll
    for (int o = 16; o > 0; o >>= 1) v += __shfl_xor_sync(0xffffffffu, v, o);
    int wid = threadIdx.x >> 5, lane = threadIdx.x & 31;
    if (lane == 0) red[wid] = v;
    __syncthreads();
    if (wid == 0) {
        v = (lane < 8) ? red[lane] : 0.f;
#pragma unroll
        for (int o = 4; o > 0; o >>= 1) v += __shfl_xor_sync(0xffffffffu, v, o);
        if (lane == 0) red[0] = v;
    }
    __syncthreads();
    return red[0];
}

__device__ __forceinline__ void norm_rope_row(
    const float* __restrict__ row, const float* __restrict__ w,
    const float* __restrict__ fcos, const float* __restrict__ fsin,
    __half* __restrict__ out, int s, float outscale) {
    const int t = threadIdx.x;
    float ss = 0.f;
    for (int j = t; j < DIMC / 4; j += 256) {
        float4 v = *(const float4*)(row + j * 4);
        ss += v.x * v.x + v.y * v.y + v.z * v.z + v.w * v.w;
    }
    ss = block_reduce_sum(ss);
    const float scale = rsqrtf(ss * (1.0f / DIMC) + 1e-6f) * outscale;

    const int f = s / HW;
    const int rem = s - f * HW;
    const int h = rem / WW;
    const int wp = rem - h * WW;

    __half2* out2 = (__half2*)out;
    for (int p = t; p < DIMC / 2; p += 256) {
        int c = p & (CP - 1);
        int pos = (c < C0P) ? f : (c < C0P + C1P) ? h : wp;
        float fc = fcos[pos * CP + c];
        float fs = fsin[pos * CP + c];
        float a = row[2 * p] * scale * w[2 * p];
        float b = row[2 * p + 1] * scale * w[2 * p + 1];
        out2[p] = __floats2half2_rn(a * fc - b * fs, a * fs + b * fc);
    }
}

__global__ void prep_fused_kernel(const float* __restrict__ wqn, const float* __restrict__ wkn,
                                  const float* __restrict__ pk, const float* __restrict__ pv,
                                  const float* __restrict__ fcos, const float* __restrict__ fsin,
                                  const int* __restrict__ hm, const int* __restrict__ shift_ptr) {
    const int b = blockIdx.x;
    const float QSCALE = 0.08838834764831845f;  // 1/sqrt(128)
    if (b < Sq) {
        norm_rope_row(g_qraw + (size_t)b * DIMC, wqn, fcos, fsin,
                      g_q + (size_t)b * DIMC, b, QSCALE);
        return;
    }
    if (b < 2 * Sq) {
        int s = b - Sq;
        norm_rope_row(g_kraw + (size_t)s * DIMC, wkn, fcos, fsin,
                      g_K + (size_t)(LC + s) * DIMC, s, 1.0f);
        return;
    }
    // cache prep
    const int l = b - 2 * Sq;
    const int t = threadIdx.x;
    const int shift = *shift_ptr;
    const int f = l / HW;
    const int rem = l - f * HW;
    const int h = rem / WW;
    const int wp = rem - h * WW;

    __half2* K2 = (__half2*)(g_K + (size_t)l * DIMC);
    __half2* V2 = (__half2*)(g_V + (size_t)l * DIMC);

    for (int p = t; p < DIMC / 2; p += 256) {
        int n = p >> 6;
        int c = p & (CP - 1);
        float m = (hm[n] != 0) ? 1.f : 0.f;
        int pos = (c < C0P) ? (shift + f) : (c < C0P + C1P) ? h : wp;
        float fc = fcos[pos * CP + c];
        float fs = fsin[pos * CP + c];
        float a = pk[(size_t)l * DIMC + 2 * p];
        float bb = pk[(size_t)l * DIMC + 2 * p + 1];
        K2[p] = __floats2half2_rn((a * fc - bb * fs) * m, (a * fs + bb * fc) * m);
    }
    for (int j = t; j < DIMC / 4; j += 256) {
        float4 v = *(const float4*)(pv + (size_t)l * DIMC + j * 4);
        int n = (j * 4) >> 7;
        float m = (hm[n] != 0) ? 1.f : 0.f;
        V2[2 * j]     = __floats2half2_rn(v.x * m, v.y * m);
        V2[2 * j + 1] = __floats2half2_rn(v.z * m, v.w * m);
    }
}

// ---------------- FP16 flash attention (3-stage pipeline, q pre-scaled) ----------------
#define QP    272                 // bytes per smem row (136 halves)
#define QBYT  (128 * QP)          // 34816
#define KOFF  QBYT
#define TILEB (64 * QP)           // 17408
#define VOFF  (KOFF + 3 * TILEB)
#define ASMEM (VOFF + 3 * TILEB)  // 139264

__global__ __launch_bounds__(256) void attn_h_kernel(
    const __half* __restrict__ Q, const __half* __restrict__ K,
    const __half* __restrict__ V, __half* __restrict__ O) {
    extern __shared__ __align__(1024) char smem[];
    const uint32_t sb = smem_u32(smem);
    const int qt = blockIdx.x, hN = blockIdx.y;
    const int t = threadIdx.x, w = t >> 5, lane = t & 31, g = lane >> 2, tg = lane & 3;
    const int rb = w * 16;

    auto load_tile = [&](int kt, int buf) {
#pragma unroll
        for (int u = 0; u < 4; u++) {
            int id = t + u * 256;
            int r = id >> 4, c = id & 15;
            cpa16(smem + KOFF + buf * TILEB + r * QP + c * 16,
                  K + (size_t)(kt * 64 + r) * DIMC + hN * HD + c * 8);
            cpa16(smem + VOFF + buf * TILEB + r * QP + c * 16,
                  V + (size_t)(kt * 64 + r) * DIMC + hN * HD + c * 8);
        }
    };

    // prologue: Q + tile0 in group 0, tile1 in group 1
#pragma unroll
    for (int u = 0; u < 8; u++) {
        int id = t + u * 256;
        int r = id >> 4, c = id & 15;
        cpa16(smem + r * QP + c * 16, Q + (size_t)(qt * 128 + r) * DIMC + hN * HD + c * 8);
    }
    load_tile(0, 0); CP_COMMIT();
    load_tile(1, 1); CP_COMMIT();

    const uint32_t qAddr = sb + (rb + (lane & 15)) * QP + (lane >> 4) * 16;
    const uint32_t kAddr = sb + KOFF + (((lane >> 4) << 3) + (lane & 7)) * QP + ((lane >> 3) & 1) * 16;
    const uint32_t vAddr = sb + VOFF + (lane & 15) * QP + (lane >> 4) * 16;

    float rm0 = -1e30f, rm1 = -1e30f, rl0 = 0.f, rl1 = 0.f;
    float o[16][4];
#pragma unroll
    for (int nj = 0; nj < 16; nj++)
#pragma unroll
        for (int r = 0; r < 4; r++) o[nj][r] = 0.f;

    int cbuf = 0, lbuf = 2;
    for (int kt = 0; kt < LT / 64; kt++) {
        CP_WAIT1();
        __syncthreads();
        if (kt + 2 < LT / 64) load_tile(kt + 2, lbuf);
        CP_COMMIT();

        const uint32_t kb = kAddr + cbuf * TILEB;
        const uint32_t vb = vAddr + cbuf * TILEB;

        // S = Q K^T (q pre-scaled)
        float s[8][4];
#pragma unroll
        for (int nj = 0; nj < 8; nj++)
#pragma unroll
            for (int r = 0; r < 4; r++) s[nj][r] = 0.f;

#pragma unroll
        for (int ks = 0; ks < 8; ks++) {
            uint32_t a[4];
            LDSM4(a[0], a[1], a[2], a[3], qAddr + ks * 32);
#pragma unroll
            for (int njp = 0; njp < 4; njp++) {
                uint32_t b[4];
                LDSM4(b[0], b[1], b[2], b[3], kb + njp * 16 * QP + ks * 32);
                mma_f16(s[2 * njp], a, b);
                mma_f16(s[2 * njp + 1], a, b + 2);
            }
        }

        // online softmax (rows g / g+8)
        float tm0 = -1e30f, tm1 = -1e30f;
#pragma unroll
        for (int nj = 0; nj < 8; nj++) {
            tm0 = fmaxf(tm0, fmaxf(s[nj][0], s[nj][1]));
            tm1 = fmaxf(tm1, fmaxf(s[nj][2], s[nj][3]));
        }
        tm0 = fmaxf(tm0, __shfl_xor_sync(0xffffffffu, tm0, 1));
        tm0 = fmaxf(tm0, __shfl_xor_sync(0xffffffffu, tm0, 2));
        tm1 = fmaxf(tm1, __shfl_xor_sync(0xffffffffu, tm1, 1));
        tm1 = fmaxf(tm1, __shfl_xor_sync(0xffffffffu, tm1, 2));
        float nm0 = fmaxf(rm0, tm0), nm1 = fmaxf(rm1, tm1);
        float corr0 = __expf(rm0 - nm0), corr1 = __expf(rm1 - nm1);

        float pf[8][4];
        float ps0 = 0.f, ps1 = 0.f;
#pragma unroll
        for (int nj = 0; nj < 8; nj++) {
            pf[nj][0] = __expf(s[nj][0] - nm0);
            pf[nj][1] = __expf(s[nj][1] - nm0);
            pf[nj][2] = __expf(s[nj][2] - nm1);
            pf[nj][3] = __expf(s[nj][3] - nm1);
            ps0 += pf[nj][0] + pf[nj][1];
            ps1 += pf[nj][2] + pf[nj][3];
        }
        ps0 += __shfl_xor_sync(0xffffffffu, ps0, 1);
        ps0 += __shfl_xor_sync(0xffffffffu, ps0, 2);
        ps1 += __shfl_xor_sync(0xffffffffu, ps1, 1);
        ps1 += __shfl_xor_sync(0xffffffffu, ps1, 2);
        rl0 = rl0 * corr0 + ps0;
        rl1 = rl1 * corr1 + ps1;
        rm0 = nm0; rm1 = nm1;

        // P C-frags -> fp16 A-frags in registers
        uint32_t pa[4][4];
#pragma unroll
        for (int kk = 0; kk < 4; kk++) {
            pa[kk][0] = packh2(pf[2 * kk][0],     pf[2 * kk][1]);
            pa[kk][1] = packh2(pf[2 * kk][2],     pf[2 * kk][3]);
            pa[kk][2] = packh2(pf[2 * kk + 1][0], pf[2 * kk + 1][1]);
            pa[kk][3] = packh2(pf[2 * kk + 1][2], pf[2 * kk + 1][3]);
        }
#pragma unroll
        for (int nj = 0; nj < 16; nj++) {
            o[nj][0] *= corr0; o[nj][1] *= corr0;
            o[nj][2] *= corr1; o[nj][3] *= corr1;
        }

        // O += P V
#pragma unroll
        for (int kk = 0; kk < 4; kk++) {
#pragma unroll
            for (int njp = 0; njp < 8; njp++) {
                uint32_t b[4];
                LDSM4T(b[0], b[1], b[2], b[3], vb + kk * 16 * QP + njp * 32);
                mma_f16(o[2 * njp], pa[kk], b);
                mma_f16(o[2 * njp + 1], pa[kk], b + 2);
            }
        }
        cbuf = (cbuf == 2) ? 0 : cbuf + 1;
        lbuf = (lbuf == 2) ? 0 : lbuf + 1;
    }

    // epilogue -> f16 ctx
    float inv0 = 1.f / rl0, inv1 = 1.f / rl1;
    int row0 = qt * 128 + rb + g;
#pragma unroll
    for (int nj = 0; nj < 16; nj++) {
        int col = hN * HD + nj * 8 + 2 * tg;
        *(__half2*)(O + (size_t)row0 * DIMC + col) =
            __floats2half2_rn(o[nj][0] * inv0, o[nj][1] * inv0);
        *(__half2*)(O + (size_t)(row0 + 8) * DIMC + col) =
            __floats2half2_rn(o[nj][2] * inv1, o[nj][3] * inv1);
    }
}

// ---------------- launch ----------------
extern "C" void kernel_launch(void* const* d_in, const int* in_sizes, int n_in,
                              void* d_out, int out_size) {
    const float* x    = (const float*)d_in[0];
    const float* Wq   = (const float*)d_in[1];
    const float* bq   = (const float*)d_in[2];
    const float* Wk   = (const float*)d_in[3];
    const float* bk   = (const float*)d_in[4];
    const float* Wv   = (const float*)d_in[5];
    const float* bv   = (const float*)d_in[6];
    const float* Wo   = (const float*)d_in[7];
    const float* bo   = (const float*)d_in[8];
    const float* wqn  = (const float*)d_in[9];
    const float* wkn  = (const float*)d_in[10];
    const float* pk   = (const float*)d_in[11];
    const float* pv   = (const float*)d_in[12];
    const float* fcos = (const float*)d_in[13];
    const float* fsin = (const float*)d_in[14];
    const int*   hm   = (const int*)d_in[15];
    const int*   shift = (const int*)d_in[18];
    float* out = (float*)d_out;

    __half *xh, *q, *Kh, *Vh, *ctx;
    cudaGetSymbolAddress((void**)&xh,  g_xh);
    cudaGetSymbolAddress((void**)&q,   g_q);
    cudaGetSymbolAddress((void**)&Kh,  g_K);
    cudaGetSymbolAddress((void**)&Vh,  g_V);
    cudaGetSymbolAddress((void**)&ctx, g_ctx);

    cudaFuncSetAttribute(hgemm_qkv_kernel, cudaFuncAttributeMaxDynamicSharedMemorySize, GSMEM);
    cudaFuncSetAttribute(hgemm_o_kernel,   cudaFuncAttributeMaxDynamicSharedMemorySize, GSMEM);
    cudaFuncSetAttribute(attn_h_kernel,    cudaFuncAttributeMaxDynamicSharedMemorySize, ASMEM);

    // 1. x -> f16
    int n4 = Sq * DIMC / 4;
    f2h_kernel<<<(n4 + 255) / 256, 256>>>(x, xh, n4);
    // 2. all weight transposes
    wtrans_all_kernel<<<dim3(DIMC / 32, DIMC / 32, 4), dim3(32, 8)>>>(Wq, Wk, Wv, Wo);
    // 3. fused QKV projection
    hgemm_qkv_kernel<<<dim3(36, Sq / BM), 256, GSMEM>>>(xh, bq, bk, bv);
    // 4. fused norm+rope+cache
    prep_fused_kernel<<<2 * Sq + LC, 256>>>(wqn, wkn, pk, pv, fcos, fsin, hm, shift);
    // 5. attention  (profiled slot)
    attn_h_kernel<<<dim3(Sq / 128, NH), 256, ASMEM>>>(q, Kh, Vh, ctx);
    // 6. output projection
    hgemm_o_kernel<<<dim3(DIMC / BN, Sq / BM), 256, GSMEM>>>(bo, out);
}

// round 9
// speedup vs baseline: 8.7035x; 1.0453x over previous
#include <cuda_runtime.h>
#include <cuda_fp16.h>
#include <math.h>
#include <stdint.h>

// ---------------- constants ----------------
#define Sq   3072
#define LC   768
#define LT   3840
#define DIMC 1536
#define NH   12
#define HD   128
#define CP   64
#define C0P  22
#define C1P  21
#define WW   24
#define HW   384

// ---------------- scratch ----------------
__device__ float  g_qraw[Sq * DIMC];
__device__ float  g_kraw[Sq * DIMC];
__device__ __half g_xh[Sq * DIMC];
__device__ __half g_q[Sq * DIMC];
__device__ __half g_K[LT * DIMC];
__device__ __half g_V[LT * DIMC];
__device__ __half g_ctx[Sq * DIMC];
__device__ __half g_WqkvT[3 * DIMC * DIMC];
__device__ __half g_WoT[DIMC * DIMC];

// ---------------- helpers ----------------
__device__ __forceinline__ uint32_t smem_u32(const void* p) {
    return (uint32_t)__cvta_generic_to_shared(p);
}
__device__ __forceinline__ void cpa16(void* s, const void* g) {
    uint32_t sa = (uint32_t)__cvta_generic_to_shared(s);
    asm volatile("cp.async.cg.shared.global [%0], [%1], 16;" :: "r"(sa), "l"(g));
}
#define CP_COMMIT() asm volatile("cp.async.commit_group;")
#define CP_WAIT0()  asm volatile("cp.async.wait_group 0;")

#define LDSM4(r0, r1, r2, r3, addr) \
    asm volatile("ldmatrix.sync.aligned.m8n8.x4.shared.b16 {%0,%1,%2,%3}, [%4];" \
                 : "=r"(r0), "=r"(r1), "=r"(r2), "=r"(r3) : "r"(addr))
#define LDSM4T(r0, r1, r2, r3, addr) \
    asm volatile("ldmatrix.sync.aligned.m8n8.x4.trans.shared.b16 {%0,%1,%2,%3}, [%4];" \
                 : "=r"(r0), "=r"(r1), "=r"(r2), "=r"(r3) : "r"(addr))

__device__ __forceinline__ void mma_f16(float* d, const uint32_t* a, const uint32_t* b) {
    asm volatile(
        "mma.sync.aligned.m16n8k16.row.col.f32.f16.f16.f32 "
        "{%0,%1,%2,%3}, {%4,%5,%6,%7}, {%8,%9}, {%0,%1,%2,%3};\n"
        : "+f"(d[0]), "+f"(d[1]), "+f"(d[2]), "+f"(d[3])
        : "r"(a[0]), "r"(a[1]), "r"(a[2]), "r"(a[3]), "r"(b[0]), "r"(b[1]));
}
__device__ __forceinline__ uint32_t packh2(float lo, float hi) {
    __half2 h = __floats2half2_rn(lo, hi);
    return *(uint32_t*)&h;
}

// ---------------- prep: transpose all weights + f2h(x) in one launch ----------------
// grid (48, 48, 5): z<4 = weight transpose slices, z==4 = x conversion
__global__ void wtrans_all_kernel(const float* __restrict__ W0, const float* __restrict__ W1,
                                  const float* __restrict__ W2, const float* __restrict__ W3,
                                  const float* __restrict__ x) {
    if (blockIdx.z == 4) {
        // f2h: 2304 blocks, 256 threads each, 2 float4 per thread
        int tid = threadIdx.y * 32 + threadIdx.x;      // FULL 256-thread linear id
        int blk = blockIdx.y * 48 + blockIdx.x;
        int base = blk * 512 + tid;                    // float4 index
        const float4* in4 = (const float4*)x;
        uint2* out4 = (uint2*)g_xh;
#pragma unroll
        for (int u = 0; u < 2; u++) {
            int i = base + u * 256;
            float4 v = in4[i];
            uint2 o;
            o.x = packh2(v.x, v.y);
            o.y = packh2(v.z, v.w);
            out4[i] = o;
        }
        return;
    }
    __shared__ float tile[32][33];
    const float* W = (blockIdx.z == 0) ? W0 : (blockIdx.z == 1) ? W1 : (blockIdx.z == 2) ? W2 : W3;
    __half* dst = (blockIdx.z < 3) ? (g_WqkvT + (size_t)blockIdx.z * DIMC * DIMC) : g_WoT;
    int n0 = blockIdx.x * 32, k0 = blockIdx.y * 32;
    int xx = threadIdx.x, y = threadIdx.y;  // 32 x 8
    for (int yy = y; yy < 32; yy += 8)
        tile[yy][xx] = W[(size_t)(k0 + yy) * DIMC + n0 + xx];
    __syncthreads();
    for (int yy = y; yy < 32; yy += 8)
        dst[(size_t)(n0 + yy) * DIMC + k0 + xx] = __float2half_rn(tile[xx][yy]);
}

// ---------------- FP16 GEMM core (2-stage, 3 CTAs/SM) ----------------
#define BM  128
#define BN  128
#define BKH 64          // halves per k-chunk
#define KP  144         // bytes per smem row (72 halves)
#define ABUFB (BM * KP) // 18432
#define GSMEM (4 * ABUFB)   // 73728
#define NCH (DIMC / BKH)    // 24

template <typename EPI>
__device__ __forceinline__ void hgemm_tile(
    const __half* A, const __half* BT, int row0, int brow0,
    char* smem, EPI epi) {
    const uint32_t sb = smem_u32(smem);
    const int t = threadIdx.x, w = t >> 5, lane = t & 31;
    const int wm = w >> 1, wn = w & 1;
    const int lr = t >> 3, lc = t & 7;

    float acc[2][8][4];
#pragma unroll
    for (int mi = 0; mi < 2; mi++)
#pragma unroll
        for (int nj = 0; nj < 8; nj++)
#pragma unroll
            for (int r = 0; r < 4; r++) acc[mi][nj][r] = 0.f;

    auto load_chunk = [&](int k0, int buf) {
#pragma unroll
        for (int u = 0; u < 4; u++) {
            int r = lr + u * 32;
            cpa16(smem + buf * ABUFB + r * KP + lc * 16,
                  A + (size_t)(row0 + r) * DIMC + k0 + lc * 8);
            cpa16(smem + 2 * ABUFB + buf * ABUFB + r * KP + lc * 16,
                  BT + (size_t)(brow0 + r) * DIMC + k0 + lc * 8);
        }
    };

    load_chunk(0, 0); CP_COMMIT();

    const uint32_t aAddr = sb + (wm * 32 + (lane & 15)) * KP + (lane >> 4) * 16;
    const uint32_t bAddr = sb + 2 * ABUFB +
        (wn * 64 + ((lane >> 4) << 3) + (lane & 7)) * KP + ((lane >> 3) & 1) * 16;

    for (int i = 0; i < NCH; i++) {
        CP_WAIT0();
        __syncthreads();
        if (i + 1 < NCH) load_chunk((i + 1) * BKH, (i + 1) & 1);
        CP_COMMIT();

        const uint32_t ab = aAddr + (i & 1) * ABUFB;
        const uint32_t bb = bAddr + (i & 1) * ABUFB;
#pragma unroll
        for (int ks = 0; ks < 4; ks++) {
            uint32_t a[2][4];
            LDSM4(a[0][0], a[0][1], a[0][2], a[0][3], ab + ks * 32);
            LDSM4(a[1][0], a[1][1], a[1][2], a[1][3], ab + 16 * KP + ks * 32);
            uint32_t b[8][2];
#pragma unroll
            for (int njp = 0; njp < 4; njp++)
                LDSM4(b[2 * njp][0], b[2 * njp][1], b[2 * njp + 1][0], b[2 * njp + 1][1],
                      bb + njp * 16 * KP + ks * 32);
#pragma unroll
            for (int mi = 0; mi < 2; mi++)
#pragma unroll
                for (int nj = 0; nj < 8; nj++) mma_f16(acc[mi][nj], a[mi], b[nj]);
        }
    }

#pragma unroll
    for (int mi = 0; mi < 2; mi++) {
#pragma unroll
        for (int hf = 0; hf < 2; hf++) {
            int rl = wm * 32 + mi * 16 + (lane >> 2) + hf * 8;
#pragma unroll
            for (int nj = 0; nj < 8; nj++) {
                int cl = wn * 64 + nj * 8 + 2 * (lane & 3);
                epi(rl, cl, acc[mi][nj][hf * 2 + 0], acc[mi][nj][hf * 2 + 1]);
            }
        }
    }
}

// fused QKV: grid (36, 24)
__global__ __launch_bounds__(256) void hgemm_qkv_kernel(
    const __half* __restrict__ xh,
    const float* __restrict__ bq, const float* __restrict__ bk, const float* __restrict__ bv) {
    extern __shared__ __align__(1024) char smem[];
    const int bx = blockIdx.x, by = blockIdx.y;
    const int seg = bx / 12, bxl = bx - seg * 12;
    const int row0 = by * BM;
    const int col0 = bxl * BN;
    const float* bias = (seg == 0) ? bq : (seg == 1) ? bk : bv;

    hgemm_tile(xh, g_WqkvT, row0, bx * BN, smem,
        [&](int rl, int cl, float v0, float v1) {
            int row = row0 + rl, col = col0 + cl;
            v0 += bias[col]; v1 += bias[col + 1];
            if (seg == 0) {
                *(float2*)(g_qraw + (size_t)row * DIMC + col) = make_float2(v0, v1);
            } else if (seg == 1) {
                *(float2*)(g_kraw + (size_t)row * DIMC + col) = make_float2(v0, v1);
            } else {
                *(__half2*)(g_V + (size_t)(LC + row) * DIMC + col) = __floats2half2_rn(v0, v1);
            }
        });
}

// O projection: grid (12, 24)
__global__ __launch_bounds__(256) void hgemm_o_kernel(
    const float* __restrict__ bo, float* __restrict__ out) {
    extern __shared__ __align__(1024) char smem[];
    const int row0 = blockIdx.y * BM, col0 = blockIdx.x * BN;
    hgemm_tile(g_ctx, g_WoT, row0, col0, smem,
        [&](int rl, int cl, float v0, float v1) {
            int row = row0 + rl, col = col0 + cl;
            *(float2*)(out + (size_t)row * DIMC + col) =
                make_float2(v0 + bo[col], v1 + bo[col + 1]);
        });
}

// ---------------- fused prep: norm_rope(q), norm_rope(k), cache ----------------
__inline__ __device__ float block_reduce_sum(float v) {
    __shared__ float red[8];
#pragma unroll
    for (int o = 16; o > 0; o >>= 1) v += __shfl_xor_sync(0xffffffffu, v, o);
    int wid = threadIdx.x >> 5, lane = threadIdx.x & 31;
    if (lane == 0) red[wid] = v;
    __syncthreads();
    if (wid == 0) {
        v = (lane < 8) ? red[lane] : 0.f;
#pragma unroll
        for (int o = 4; o > 0; o >>= 1) v += __shfl_xor_sync(0xffffffffu, v, o);
        if (lane == 0) red[0] = v;
    }
    __syncthreads();
    return red[0];
}

__device__ __forceinline__ void norm_rope_row(
    const float* __restrict__ row, const float* __restrict__ w,
    const float* __restrict__ fcos, const float* __restrict__ fsin,
    __half* __restrict__ out, int s, float outscale) {
    const int t = threadIdx.x;
    float ss = 0.f;
    for (int j = t; j < DIMC / 4; j += 256) {
        float4 v = *(const float4*)(row + j * 4);
        ss += v.x * v.x + v.y * v.y + v.z * v.z + v.w * v.w;
    }
    ss = block_reduce_sum(ss);
    const float scale = rsqrtf(ss * (1.0f / DIMC) + 1e-6f) * outscale;

    const int f = s / HW;
    const int rem = s - f * HW;
    const int h = rem / WW;
    const int wp = rem - h * WW;

    __half2* out2 = (__half2*)out;
    for (int p = t; p < DIMC / 2; p += 256) {
        int c = p & (CP - 1);
        int pos = (c < C0P) ? f : (c < C0P + C1P) ? h : wp;
        float fc = fcos[pos * CP + c];
        float fs = fsin[pos * CP + c];
        float a = row[2 * p] * scale * w[2 * p];
        float b = row[2 * p + 1] * scale * w[2 * p + 1];
        out2[p] = __floats2half2_rn(a * fc - b * fs, a * fs + b * fc);
    }
}

__global__ void prep_fused_kernel(const float* __restrict__ wqn, const float* __restrict__ wkn,
                                  const float* __restrict__ pk, const float* __restrict__ pv,
                                  const float* __restrict__ fcos, const float* __restrict__ fsin,
                                  const int* __restrict__ hm, const int* __restrict__ shift_ptr) {
    const int b = blockIdx.x;
    const float QSCALE = 0.08838834764831845f;  // 1/sqrt(128)
    if (b < Sq) {
        norm_rope_row(g_qraw + (size_t)b * DIMC, wqn, fcos, fsin,
                      g_q + (size_t)b * DIMC, b, QSCALE);
        return;
    }
    if (b < 2 * Sq) {
        int s = b - Sq;
        norm_rope_row(g_kraw + (size_t)s * DIMC, wkn, fcos, fsin,
                      g_K + (size_t)(LC + s) * DIMC, s, 1.0f);
        return;
    }
    // cache prep
    const int l = b - 2 * Sq;
    const int t = threadIdx.x;
    const int shift = *shift_ptr;
    const int f = l / HW;
    const int rem = l - f * HW;
    const int h = rem / WW;
    const int wp = rem - h * WW;

    __half2* K2 = (__half2*)(g_K + (size_t)l * DIMC);
    __half2* V2 = (__half2*)(g_V + (size_t)l * DIMC);

    for (int p = t; p < DIMC / 2; p += 256) {
        int n = p >> 6;
        int c = p & (CP - 1);
        float m = (hm[n] != 0) ? 1.f : 0.f;
        int pos = (c < C0P) ? (shift + f) : (c < C0P + C1P) ? h : wp;
        float fc = fcos[pos * CP + c];
        float fs = fsin[pos * CP + c];
        float a = pk[(size_t)l * DIMC + 2 * p];
        float bb = pk[(size_t)l * DIMC + 2 * p + 1];
        K2[p] = __floats2half2_rn((a * fc - bb * fs) * m, (a * fs + bb * fc) * m);
    }
    for (int j = t; j < DIMC / 4; j += 256) {
        float4 v = *(const float4*)(pv + (size_t)l * DIMC + j * 4);
        int n = (j * 4) >> 7;
        float m = (hm[n] != 0) ? 1.f : 0.f;
        V2[2 * j]     = __floats2half2_rn(v.x * m, v.y * m);
        V2[2 * j + 1] = __floats2half2_rn(v.z * m, v.w * m);
    }
}

// ---------------- FP16 flash attention (double-buffered, 2 CTAs/SM) ----------------
#define QP    272                 // bytes per smem row (136 halves)
#define QBYT  (128 * QP)          // 34816
#define KOFF  QBYT
#define TILEB (64 * QP)           // 17408
#define VOFF  (KOFF + 2 * TILEB)
#define ASMEM (VOFF + 2 * TILEB)  // 104448

__global__ __launch_bounds__(256) void attn_h_kernel(
    const __half* __restrict__ Q, const __half* __restrict__ K,
    const __half* __restrict__ V, __half* __restrict__ O) {
    extern __shared__ __align__(1024) char smem[];
    const uint32_t sb = smem_u32(smem);
    const int qt = blockIdx.x, hN = blockIdx.y;
    const int t = threadIdx.x, w = t >> 5, lane = t & 31, g = lane >> 2, tg = lane & 3;
    const int rb = w * 16;

    auto load_tile = [&](int kt, int buf) {
#pragma unroll
        for (int u = 0; u < 4; u++) {
            int id = t + u * 256;
            int r = id >> 4, c = id & 15;
            cpa16(smem + KOFF + buf * TILEB + r * QP + c * 16,
                  K + (size_t)(kt * 64 + r) * DIMC + hN * HD + c * 8);
            cpa16(smem + VOFF + buf * TILEB + r * QP + c * 16,
                  V + (size_t)(kt * 64 + r) * DIMC + hN * HD + c * 8);
        }
    };

#pragma unroll
    for (int u = 0; u < 8; u++) {
        int id = t + u * 256;
        int r = id >> 4, c = id & 15;
        cpa16(smem + r * QP + c * 16, Q + (size_t)(qt * 128 + r) * DIMC + hN * HD + c * 8);
    }
    load_tile(0, 0);
    CP_COMMIT();

    const uint32_t qAddr = sb + (rb + (lane & 15)) * QP + (lane >> 4) * 16;
    const uint32_t kAddr = sb + KOFF + (((lane >> 4) << 3) + (lane & 7)) * QP + ((lane >> 3) & 1) * 16;
    const uint32_t vAddr = sb + VOFF + (lane & 15) * QP + (lane >> 4) * 16;

    float rm0 = -1e30f, rm1 = -1e30f, rl0 = 0.f, rl1 = 0.f;
    float o[16][4];
#pragma unroll
    for (int nj = 0; nj < 16; nj++)
#pragma unroll
        for (int r = 0; r < 4; r++) o[nj][r] = 0.f;

    for (int kt = 0; kt < LT / 64; kt++) {
        CP_WAIT0();
        __syncthreads();
        if (kt + 1 < LT / 64) load_tile(kt + 1, (kt + 1) & 1);
        CP_COMMIT();

        const uint32_t kb = kAddr + (kt & 1) * TILEB;
        const uint32_t vb = vAddr + (kt & 1) * TILEB;

        // S = Q K^T (q pre-scaled by 1/sqrt(d))
        float s[8][4];
#pragma unroll
        for (int nj = 0; nj < 8; nj++)
#pragma unroll
            for (int r = 0; r < 4; r++) s[nj][r] = 0.f;

#pragma unroll
        for (int ks = 0; ks < 8; ks++) {
            uint32_t a[4];
            LDSM4(a[0], a[1], a[2], a[3], qAddr + ks * 32);
#pragma unroll
            for (int njp = 0; njp < 4; njp++) {
                uint32_t b[4];
                LDSM4(b[0], b[1], b[2], b[3], kb + njp * 16 * QP + ks * 32);
                mma_f16(s[2 * njp], a, b);
                mma_f16(s[2 * njp + 1], a, b + 2);
            }
        }

        // online softmax (rows g / g+8)
        float tm0 = -1e30f, tm1 = -1e30f;
#pragma unroll
        for (int nj = 0; nj < 8; nj++) {
            tm0 = fmaxf(tm0, fmaxf(s[nj][0], s[nj][1]));
            tm1 = fmaxf(tm1, fmaxf(s[nj][2], s[nj][3]));
        }
        tm0 = fmaxf(tm0, __shfl_xor_sync(0xffffffffu, tm0, 1));
        tm0 = fmaxf(tm0, __shfl_xor_sync(0xffffffffu, tm0, 2));
        tm1 = fmaxf(tm1, __shfl_xor_sync(0xffffffffu, tm1, 1));
        tm1 = fmaxf(tm1, __shfl_xor_sync(0xffffffffu, tm1, 2));
        float nm0 = fmaxf(rm0, tm0), nm1 = fmaxf(rm1, tm1);
        float corr0 = __expf(rm0 - nm0), corr1 = __expf(rm1 - nm1);

        float pf[8][4];
        float ps0 = 0.f, ps1 = 0.f;
#pragma unroll
        for (int nj = 0; nj < 8; nj++) {
            pf[nj][0] = __expf(s[nj][0] - nm0);
            pf[nj][1] = __expf(s[nj][1] - nm0);
            pf[nj][2] = __expf(s[nj][2] - nm1);
            pf[nj][3] = __expf(s[nj][3] - nm1);
            ps0 += pf[nj][0] + pf[nj][1];
            ps1 += pf[nj][2] + pf[nj][3];
        }
        ps0 += __shfl_xor_sync(0xffffffffu, ps0, 1);
        ps0 += __shfl_xor_sync(0xffffffffu, ps0, 2);
        ps1 += __shfl_xor_sync(0xffffffffu, ps1, 1);
        ps1 += __shfl_xor_sync(0xffffffffu, ps1, 2);
        rl0 = rl0 * corr0 + ps0;
        rl1 = rl1 * corr1 + ps1;
        rm0 = nm0; rm1 = nm1;

        // P C-frags -> fp16 A-frags in registers
        uint32_t pa[4][4];
#pragma unroll
        for (int kk = 0; kk < 4; kk++) {
            pa[kk][0] = packh2(pf[2 * kk][0],     pf[2 * kk][1]);
            pa[kk][1] = packh2(pf[2 * kk][2],     pf[2 * kk][3]);
            pa[kk][2] = packh2(pf[2 * kk + 1][0], pf[2 * kk + 1][1]);
            pa[kk][3] = packh2(pf[2 * kk + 1][2], pf[2 * kk + 1][3]);
        }
#pragma unroll
        for (int nj = 0; nj < 16; nj++) {
            o[nj][0] *= corr0; o[nj][1] *= corr0;
            o[nj][2] *= corr1; o[nj][3] *= corr1;
        }

        // O += P V
#pragma unroll
        for (int kk = 0; kk < 4; kk++) {
#pragma unroll
            for (int njp = 0; njp < 8; njp++) {
                uint32_t b[4];
                LDSM4T(b[0], b[1], b[2], b[3], vb + kk * 16 * QP + njp * 32);
                mma_f16(o[2 * njp], pa[kk], b);
                mma_f16(o[2 * njp + 1], pa[kk], b + 2);
            }
        }
    }

    // epilogue -> f16 ctx
    float inv0 = 1.f / rl0, inv1 = 1.f / rl1;
    int row0 = qt * 128 + rb + g;
#pragma unroll
    for (int nj = 0; nj < 16; nj++) {
        int col = hN * HD + nj * 8 + 2 * tg;
        *(__half2*)(O + (size_t)row0 * DIMC + col) =
            __floats2half2_rn(o[nj][0] * inv0, o[nj][1] * inv0);
        *(__half2*)(O + (size_t)(row0 + 8) * DIMC + col) =
            __floats2half2_rn(o[nj][2] * inv1, o[nj][3] * inv1);
    }
}

// ---------------- launch ----------------
extern "C" void kernel_launch(void* const* d_in, const int* in_sizes, int n_in,
                              void* d_out, int out_size) {
    const float* x    = (const float*)d_in[0];
    const float* Wq   = (const float*)d_in[1];
    const float* bq   = (const float*)d_in[2];
    const float* Wk   = (const float*)d_in[3];
    const float* bk   = (const float*)d_in[4];
    const float* Wv   = (const float*)d_in[5];
    const float* bv   = (const float*)d_in[6];
    const float* Wo   = (const float*)d_in[7];
    const float* bo   = (const float*)d_in[8];
    const float* wqn  = (const float*)d_in[9];
    const float* wkn  = (const float*)d_in[10];
    const float* pk   = (const float*)d_in[11];
    const float* pv   = (const float*)d_in[12];
    const float* fcos = (const float*)d_in[13];
    const float* fsin = (const float*)d_in[14];
    const int*   hm   = (const int*)d_in[15];
    const int*   shift = (const int*)d_in[18];
    float* out = (float*)d_out;

    __half *xh, *q, *Kh, *Vh, *ctx;
    cudaGetSymbolAddress((void**)&xh,  g_xh);
    cudaGetSymbolAddress((void**)&q,   g_q);
    cudaGetSymbolAddress((void**)&Kh,  g_K);
    cudaGetSymbolAddress((void**)&Vh,  g_V);
    cudaGetSymbolAddress((void**)&ctx, g_ctx);

    cudaFuncSetAttribute(hgemm_qkv_kernel, cudaFuncAttributeMaxDynamicSharedMemorySize, GSMEM);
    cudaFuncSetAttribute(hgemm_o_kernel,   cudaFuncAttributeMaxDynamicSharedMemorySize, GSMEM);
    cudaFuncSetAttribute(attn_h_kernel,    cudaFuncAttributeMaxDynamicSharedMemorySize, ASMEM);

    // 1. weight transposes + x->f16 (one launch)
    wtrans_all_kernel<<<dim3(48, 48, 5), dim3(32, 8)>>>(Wq, Wk, Wv, Wo, x);
    // 2. fused QKV projection
    hgemm_qkv_kernel<<<dim3(36, Sq / BM), 256, GSMEM>>>(xh, bq, bk, bv);
    // 3. fused norm+rope+cache
    prep_fused_kernel<<<2 * Sq + LC, 256>>>(wqn, wkn, pk, pv, fcos, fsin, hm, shift);
    // 4. attention  (profiled slot)
    attn_h_kernel<<<dim3(Sq / 128, NH), 256, ASMEM>>>(q, Kh, Vh, ctx);
    // 5. output projection
    hgemm_o_kernel<<<dim3(DIMC / BN, Sq / BM), 256, GSMEM>>>(bo, out);
}